// round 9
// baseline (speedup 1.0000x reference)
#include <cuda_runtime.h>
#include <cuda_fp16.h>
#include <cstdint>

#define E_TOT   300000
#define N_NODES 50000
#define NPAD    (N_NODES + 128)
#define TILE_M  64
#define NTH     256

__device__ __half g_nodeH[(size_t)NPAD * 128];
__device__ __half g_P[(size_t)NPAD * 512];     // [node][ Ps(256) | Pr(256) ] fp16
__device__ __half g_W1sT[256 * 128];           // [n][k]
__device__ __half g_W1rT[256 * 128];
__device__ __half g_W1eT[256 * 128];
__device__ __half g_W2T[128 * 256];

// ---- main-kernel smem byte offsets ----
#define OF_B1  0         // 256 f
#define OF_B2  1024      // 128 f
#define OF_G   1536      // 128 f
#define OF_BT  2048      // 128 f
#define OF_SI  2560      // 64 i
#define OF_RI  2816      // 64 i
#define OF_X0  3072      // 64*40 half = 5120
#define OF_X1  8192
#define OF_W0  13312     // 256*40 half = 20480
#define OF_W1B 33792
#define OF_H   54272     // 64*264 half = 33792 (reused as float scratch 64*132)
#define SMEM_BYTES (OF_H + 64*264*2)        // 88064

// ---- precompute-kernel smem byte offsets ----
#define PF_X0  0         // 128*40 half = 10240
#define PF_X1  10240
#define PF_W0  20480     // 256*40 half
#define PF_W1B 40960
#define SMEM_PRE (PF_W1B + 20480)           // 61440

#define XS 40
#define WS 40
#define HS 264
#define OS 132

__device__ __forceinline__ uint32_t smem_u32(const void* p) {
    uint32_t a;
    asm("{ .reg .u64 t; cvta.to.shared.u64 t, %1; cvt.u32.u64 %0, t; }" : "=r"(a) : "l"(p));
    return a;
}
__device__ __forceinline__ uint32_t pkh2(float lo, float hi) {
    uint32_t r; asm("cvt.rn.f16x2.f32 %0, %1, %2;" : "=r"(r) : "f"(hi), "f"(lo)); return r;
}
__device__ __forceinline__ void mma16(float (&d)[4], const uint32_t (&a)[4],
                                      uint32_t b0, uint32_t b1) {
    asm volatile("mma.sync.aligned.m16n8k16.row.col.f32.f16.f16.f32 "
        "{%0,%1,%2,%3}, {%4,%5,%6,%7}, {%8,%9}, {%0,%1,%2,%3};"
        : "+f"(d[0]), "+f"(d[1]), "+f"(d[2]), "+f"(d[3])
        : "r"(a[0]), "r"(a[1]), "r"(a[2]), "r"(a[3]), "r"(b0), "r"(b1));
}
__device__ __forceinline__ void ldsm4(uint32_t (&r)[4], uint32_t addr) {
    asm volatile("ldmatrix.sync.aligned.m8n8.x4.shared.b16 {%0,%1,%2,%3}, [%4];"
        : "=r"(r[0]), "=r"(r[1]), "=r"(r[2]), "=r"(r[3]) : "r"(addr));
}
#define CP16(dst, src) asm volatile("cp.async.ca.shared.global [%0], [%1], 16;" :: "r"(dst), "l"(src) : "memory")
#define CP_COMMIT()    asm volatile("cp.async.commit_group;" ::: "memory")
#define CP_WAIT0()     asm volatile("cp.async.wait_group 0;" ::: "memory")
#define STSV4(a, v)    asm volatile("st.shared.v4.b32 [%0], {%1,%2,%3,%4};" :: "r"(a), "r"((v).x), "r"((v).y), "r"((v).z), "r"((v).w) : "memory")

// ---------------- cvt: node->fp16, W1 split+transpose, W2 transpose ----------------
__global__ void cvt_all_kernel(const float* __restrict__ node,
                               const float* __restrict__ W1,
                               const float* __restrict__ W2) {
    const int NODE8 = N_NODES * 128 / 8;
    const int WTOT  = 4 * 32768;
    for (int i = blockIdx.x * blockDim.x + threadIdx.x; i < NODE8 + WTOT;
         i += gridDim.x * blockDim.x) {
        if (i < NODE8) {
            float4 a = *(const float4*)(node + 8 * (size_t)i);
            float4 b = *(const float4*)(node + 8 * (size_t)i + 4);
            uint4 o;
            o.x = pkh2(a.x, a.y); o.y = pkh2(a.z, a.w);
            o.z = pkh2(b.x, b.y); o.w = pkh2(b.z, b.w);
            *(uint4*)(g_nodeH + 8 * (size_t)i) = o;
        } else {
            int j = i - NODE8;
            if (j < 3 * 32768) {
                int sec = j >> 15, m = j & 32767;
                int n = m >> 7, k = m & 127;
                float v = W1[(sec * 128 + k) * 256 + n];
                __half* dst = (sec == 0) ? g_W1sT : (sec == 1) ? g_W1rT : g_W1eT;
                dst[m] = __float2half_rn(v);
            } else {
                int m = j - 3 * 32768;
                int n = m >> 8, k = m & 255;
                g_W2T[m] = __float2half_rn(W2[k * 128 + n]);
            }
        }
    }
}

// ---------------- precompute: P[n] = node[n] @ [W1s | W1r] (512 thr) ----------------
__global__ __launch_bounds__(512, 1)
void precompute_kernel()
{
    extern __shared__ char smem[];
    const int tid = threadIdx.x;
    const int wid = tid >> 5, lane = tid & 31;
    const int lr = lane >> 2, lc = lane & 3;
    const int wm = wid >> 2, wn = wid & 3;
    const int n0 = blockIdx.x * 128;
    const __half* WT = blockIdx.y ? g_W1rT : g_W1sT;

    const int r = tid >> 2, q = tid & 3;
    const __half* pA = g_nodeH + (size_t)(n0 + r) * 128 + q * 8;
    const __half* pW = WT + (size_t)(tid >> 1) * 128 + (tid & 1) * 16;

    const uint32_t sbX[2] = { smem_u32(smem + PF_X0), smem_u32(smem + PF_X1) };
    const uint32_t sbW[2] = { smem_u32(smem + PF_W0), smem_u32(smem + PF_W1B) };
    const uint32_t dX = (uint32_t)(r * XS + q * 8) * 2;
    const uint32_t dW = (uint32_t)((tid >> 1) * WS + (tid & 1) * 16) * 2;

    const int aoff_row = lane & 15;
    const int aoff_k   = (lane >> 4) << 3;
    const int boff_n   = ((lane >> 4) << 3) + (lane & 7);
    const int boff_k   = ((lane >> 3) & 1) << 3;

    CP16(sbX[0] + dX, pA);
    CP16(sbW[0] + dW,      pW);
    CP16(sbW[0] + dW + 16, pW + 8);
    CP_COMMIT(); CP_WAIT0();
    __syncthreads();

    float acc[2][8][4];
    #pragma unroll
    for (int i = 0; i < 2; i++)
        #pragma unroll
        for (int j = 0; j < 8; j++)
            #pragma unroll
            for (int qq = 0; qq < 4; qq++) acc[i][j][qq] = 0.f;

    for (int c = 0; c < 4; c++) {
        if (c < 3) {
            CP16(sbX[(c + 1) & 1] + dX, pA + (c + 1) * 32);
            CP16(sbW[(c + 1) & 1] + dW,      pW + (c + 1) * 32);
            CP16(sbW[(c + 1) & 1] + dW + 16, pW + (c + 1) * 32 + 8);
            CP_COMMIT();
        }
        const uint32_t xb = sbX[c & 1], wb = sbW[c & 1];
        #pragma unroll
        for (int ks = 0; ks < 2; ks++) {
            uint32_t A[2][4];
            #pragma unroll
            for (int i = 0; i < 2; i++)
                ldsm4(A[i], xb + (uint32_t)((wm * 32 + i * 16 + aoff_row) * XS + ks * 16 + aoff_k) * 2);
            #pragma unroll
            for (int jp = 0; jp < 4; jp++) {
                uint32_t B[4];
                ldsm4(B, wb + (uint32_t)((wn * 64 + jp * 16 + boff_n) * WS + ks * 16 + boff_k) * 2);
                mma16(acc[0][2 * jp],     A[0], B[0], B[1]);
                mma16(acc[1][2 * jp],     A[1], B[0], B[1]);
                mma16(acc[0][2 * jp + 1], A[0], B[2], B[3]);
                mma16(acc[1][2 * jp + 1], A[1], B[2], B[3]);
            }
        }
        if (c < 3) CP_WAIT0();
        __syncthreads();
    }

    const int cbase = blockIdx.y * 256;
    #pragma unroll
    for (int i = 0; i < 2; i++) {
        int row = n0 + wm * 32 + i * 16 + lr;
        #pragma unroll
        for (int j = 0; j < 8; j++) {
            int col = wn * 64 + j * 8 + 2 * lc;
            if (row < N_NODES)
                *(uint32_t*)(g_P + (size_t)row * 512 + cbase + col) = pkh2(acc[i][j][0], acc[i][j][1]);
            if (row + 8 < N_NODES)
                *(uint32_t*)(g_P + (size_t)(row + 8) * 512 + cbase + col) = pkh2(acc[i][j][2], acc[i][j][3]);
        }
    }
}

// ---------------- main kernel: 64 edges/CTA, 2 CTAs/SM ----------------
__global__ __launch_bounds__(NTH, 2)
void edge_mlp_h(const float* __restrict__ edge_attr,
                const int*   __restrict__ eidx,
                const float* __restrict__ b1,
                const float* __restrict__ b2,
                const float* __restrict__ gamma,
                const float* __restrict__ beta,
                float* __restrict__ out)
{
    extern __shared__ char smem[];
    float* smf = (float*)smem;
    const int tid = threadIdx.x;
    const int wid = tid >> 5, lane = tid & 31;
    const int lr = lane >> 2, lc = lane & 3;
    const int wm = wid >> 2, wn = wid & 3;   // wm 0..1 rows, wn 0..3 cols
    const int e0 = blockIdx.x * TILE_M;

    if (tid < 256) smf[OF_B1 / 4 + tid] = b1[tid];
    if (tid < 128) {
        smf[OF_B2 / 4 + tid] = b2[tid];
        smf[OF_G  / 4 + tid] = gamma[tid];
        smf[OF_BT / 4 + tid] = beta[tid];
    }
    if (tid < 64) {
        int e = e0 + tid;
        bool ok = e < E_TOT;
        ((int*)(smem + OF_SI))[tid] = ok ? eidx[e] : 0;
        ((int*)(smem + OF_RI))[tid] = ok ? eidx[E_TOT + e] : 0;
    }

    const int r = tid >> 2, q = tid & 3;              // X rows 0..63
    int eMine = e0 + r; if (eMine >= E_TOT) eMine = e0;
    const float*  pE   = edge_attr + (size_t)eMine * 128 + q * 8;
    const __half* pW1e = g_W1eT + (size_t)tid * 128;                    // 4 cp16
    const __half* pW2  = g_W2T + (size_t)(tid >> 1) * 256 + (tid & 1) * 16;  // 2 cp16

    const uint32_t sbX[2] = { smem_u32(smem + OF_X0), smem_u32(smem + OF_X1) };
    const uint32_t sbW[2] = { smem_u32(smem + OF_W0), smem_u32(smem + OF_W1B) };
    const uint32_t sbH    = smem_u32(smem + OF_H);
    const uint32_t dX  = (uint32_t)(r * XS + q * 8) * 2;
    const uint32_t dW1 = (uint32_t)(tid * WS) * 2;
    const uint32_t dW2 = (uint32_t)((tid >> 1) * WS + (tid & 1) * 16) * 2;

    const int aoff_row = lane & 15;
    const int aoff_k   = (lane >> 4) << 3;
    const int boff_n   = ((lane >> 4) << 3) + (lane & 7);
    const int boff_k   = ((lane >> 3) & 1) << 3;

    // prologue: stage chunk 0 (edge cols 0..31 + W1e panel 0)
    {
        float4 e0v = *(const float4*)pE;
        float4 e1v = *(const float4*)(pE + 4);
        uint4 o;
        o.x = pkh2(e0v.x, e0v.y); o.y = pkh2(e0v.z, e0v.w);
        o.z = pkh2(e1v.x, e1v.y); o.w = pkh2(e1v.z, e1v.w);
        STSV4(sbX[0] + dX, o);
        #pragma unroll
        for (int s = 0; s < 4; s++) CP16(sbW[0] + dW1 + 16 * s, pW1e + 8 * s);
        CP_COMMIT(); CP_WAIT0();
    }
    __syncthreads();

    // ======== GEMM1e: accE[64x256] = E[64x128] @ W1e ========
    float acc[2][8][4];
    #pragma unroll
    for (int i = 0; i < 2; i++)
        #pragma unroll
        for (int j = 0; j < 8; j++)
            #pragma unroll
            for (int qq = 0; qq < 4; qq++) acc[i][j][qq] = 0.f;

    for (int c = 0; c < 4; c++) {
        const bool pre = c < 3;
        float4 ev0, ev1;
        if (pre) {
            const float* src = pE + (c + 1) * 32;
            ev0 = *(const float4*)src;
            ev1 = *(const float4*)(src + 4);
            #pragma unroll
            for (int s = 0; s < 4; s++)
                CP16(sbW[(c + 1) & 1] + dW1 + 16 * s, pW1e + (c + 1) * 32 + 8 * s);
            CP_COMMIT();
        }
        const uint32_t xb = sbX[c & 1], wb = sbW[c & 1];
        #pragma unroll
        for (int ks = 0; ks < 2; ks++) {
            uint32_t A[2][4];
            #pragma unroll
            for (int i = 0; i < 2; i++)
                ldsm4(A[i], xb + (uint32_t)((wm * 32 + i * 16 + aoff_row) * XS + ks * 16 + aoff_k) * 2);
            #pragma unroll
            for (int jp = 0; jp < 4; jp++) {
                uint32_t B[4];
                ldsm4(B, wb + (uint32_t)((wn * 64 + jp * 16 + boff_n) * WS + ks * 16 + boff_k) * 2);
                mma16(acc[0][2 * jp],     A[0], B[0], B[1]);
                mma16(acc[1][2 * jp],     A[1], B[0], B[1]);
                mma16(acc[0][2 * jp + 1], A[0], B[2], B[3]);
                mma16(acc[1][2 * jp + 1], A[1], B[2], B[3]);
            }
        }
        if (pre) {
            uint4 o;
            o.x = pkh2(ev0.x, ev0.y); o.y = pkh2(ev0.z, ev0.w);
            o.z = pkh2(ev1.x, ev1.y); o.w = pkh2(ev1.z, ev1.w);
            STSV4(sbX[(c + 1) & 1] + dX, o);
            CP_WAIT0();
        }
        __syncthreads();
    }

    // ======== epilogue 1: H = fp16(relu(accE + Ps + Pr + b1)) ========
    {
        __half* Hh = (__half*)(smem + OF_H);
        const int* sI = (const int*)(smem + OF_SI);
        const int* rI = (const int*)(smem + OF_RI);
        CP16(sbW[0] + dW2,      pW2);
        CP16(sbW[0] + dW2 + 16, pW2 + 8);
        CP_COMMIT();
        #pragma unroll
        for (int i = 0; i < 2; i++) {
            int r0 = wm * 32 + i * 16 + lr;
            const __half* P0s = g_P + (size_t)sI[r0] * 512;
            const __half* P0r = g_P + (size_t)rI[r0] * 512 + 256;
            const __half* P1s = g_P + (size_t)sI[r0 + 8] * 512;
            const __half* P1r = g_P + (size_t)rI[r0 + 8] * 512 + 256;
            #pragma unroll
            for (int j = 0; j < 8; j++) {
                int col = wn * 64 + j * 8 + 2 * lc;
                float2 ps0 = __half22float2(*(const __half2*)(P0s + col));
                float2 pr0 = __half22float2(*(const __half2*)(P0r + col));
                float2 ps1 = __half22float2(*(const __half2*)(P1s + col));
                float2 pr1 = __half22float2(*(const __half2*)(P1r + col));
                float g0 = smf[OF_B1 / 4 + col], g1 = smf[OF_B1 / 4 + col + 1];
                *(uint32_t*)(Hh + r0 * HS + col) =
                    pkh2(fmaxf(acc[i][j][0] + ps0.x + pr0.x + g0, 0.f),
                         fmaxf(acc[i][j][1] + ps0.y + pr0.y + g1, 0.f));
                *(uint32_t*)(Hh + (r0 + 8) * HS + col) =
                    pkh2(fmaxf(acc[i][j][2] + ps1.x + pr1.x + g0, 0.f),
                         fmaxf(acc[i][j][3] + ps1.y + pr1.y + g1, 0.f));
            }
        }
        CP_WAIT0();
    }
    __syncthreads();

    // ======== GEMM2: C2[64x128] = H[64x256] @ W2 ========
    float acc2[2][4][4];
    #pragma unroll
    for (int i = 0; i < 2; i++)
        #pragma unroll
        for (int j = 0; j < 4; j++)
            #pragma unroll
            for (int qq = 0; qq < 4; qq++) acc2[i][j][qq] = 0.f;

    for (int c = 0; c < 8; c++) {
        if (c < 7) {
            CP16(sbW[(c + 1) & 1] + dW2,      pW2 + (c + 1) * 32);
            CP16(sbW[(c + 1) & 1] + dW2 + 16, pW2 + (c + 1) * 32 + 8);
            CP_COMMIT();
        }
        const uint32_t wb = sbW[c & 1];
        #pragma unroll
        for (int ks = 0; ks < 2; ks++) {
            uint32_t A[2][4];
            #pragma unroll
            for (int i = 0; i < 2; i++)
                ldsm4(A[i], sbH + (uint32_t)((wm * 32 + i * 16 + aoff_row) * HS + c * 32 + ks * 16 + aoff_k) * 2);
            #pragma unroll
            for (int jp = 0; jp < 2; jp++) {
                uint32_t B[4];
                ldsm4(B, wb + (uint32_t)((wn * 32 + jp * 16 + boff_n) * WS + ks * 16 + boff_k) * 2);
                mma16(acc2[0][2 * jp],     A[0], B[0], B[1]);
                mma16(acc2[1][2 * jp],     A[1], B[0], B[1]);
                mma16(acc2[0][2 * jp + 1], A[0], B[2], B[3]);
                mma16(acc2[1][2 * jp + 1], A[1], B[2], B[3]);
            }
        }
        if (c < 7) CP_WAIT0();
        __syncthreads();
    }

    // ======== epilogue 2: scratch = C2 + b2 ; LayerNorm -> out ========
    {
        float* Of = (float*)(smem + OF_H);
        #pragma unroll
        for (int i = 0; i < 2; i++) {
            int r0 = wm * 32 + i * 16 + lr;
            #pragma unroll
            for (int j = 0; j < 4; j++) {
                int col = wn * 32 + j * 8 + 2 * lc;
                float g0 = smf[OF_B2 / 4 + col], g1 = smf[OF_B2 / 4 + col + 1];
                Of[r0 * OS + col]           = acc2[i][j][0] + g0;
                Of[r0 * OS + col + 1]       = acc2[i][j][1] + g1;
                Of[(r0 + 8) * OS + col]     = acc2[i][j][2] + g0;
                Of[(r0 + 8) * OS + col + 1] = acc2[i][j][3] + g1;
            }
        }
    }
    __syncthreads();
    {
        const float* Of = (const float*)(smem + OF_H);
        float4 ga = *(const float4*)(smf + OF_G  / 4 + 4 * lane);
        float4 bt = *(const float4*)(smf + OF_BT / 4 + 4 * lane);
        #pragma unroll
        for (int rr = 0; rr < 8; rr++) {
            int row = wid * 8 + rr;
            int e = e0 + row;
            float4 v = *(const float4*)(Of + row * OS + 4 * lane);
            float s = v.x + v.y + v.z + v.w;
            float qs = v.x * v.x + v.y * v.y + v.z * v.z + v.w * v.w;
            #pragma unroll
            for (int o = 16; o > 0; o >>= 1) {
                s  += __shfl_xor_sync(0xffffffffu, s, o);
                qs += __shfl_xor_sync(0xffffffffu, qs, o);
            }
            float mean = s * (1.0f / 128.0f);
            float var  = qs * (1.0f / 128.0f) - mean * mean;
            float inv  = rsqrtf(var + 1e-5f);
            if (e < E_TOT) {
                float4 o4;
                o4.x = (v.x - mean) * inv * ga.x + bt.x;
                o4.y = (v.y - mean) * inv * ga.y + bt.y;
                o4.z = (v.z - mean) * inv * ga.z + bt.z;
                o4.w = (v.w - mean) * inv * ga.w + bt.w;
                *(float4*)(out + (size_t)e * 128 + 4 * lane) = o4;
            }
        }
    }
}

extern "C" void kernel_launch(void* const* d_in, const int* in_sizes, int n_in,
                              void* d_out, int out_size)
{
    (void)in_sizes; (void)n_in; (void)out_size;
    cvt_all_kernel<<<2048, 256>>>((const float*)d_in[0],
                                  (const float*)d_in[3],
                                  (const float*)d_in[5]);
    cudaFuncSetAttribute(precompute_kernel,
                         cudaFuncAttributeMaxDynamicSharedMemorySize, SMEM_PRE);
    precompute_kernel<<<dim3((N_NODES + 127) / 128, 2), 512, SMEM_PRE>>>();
    cudaFuncSetAttribute(edge_mlp_h,
                         cudaFuncAttributeMaxDynamicSharedMemorySize, SMEM_BYTES);
    dim3 grid((E_TOT + TILE_M - 1) / TILE_M);
    edge_mlp_h<<<grid, NTH, SMEM_BYTES>>>(
        (const float*)d_in[1],   // edge_contact_attr
        (const int*)  d_in[2],   // edge_contact_index
        (const float*)d_in[4],   // b1
        (const float*)d_in[6],   // b2
        (const float*)d_in[7],   // ln_gamma
        (const float*)d_in[8],   // ln_beta
        (float*)d_out);
}

// round 11
// speedup vs baseline: 1.0197x; 1.0197x over previous
#include <cuda_runtime.h>
#include <cuda_fp16.h>
#include <cstdint>

#define E_TOT   300000
#define N_NODES 50000
#define NPAD    (N_NODES + 128)
#define TILE_M  128
#define NTH     512

__device__ __half g_nodeH[(size_t)NPAD * 128];
__device__ __half g_P[(size_t)NPAD * 512];     // [node][ Ps(256 perm) | Pr(256 perm) ]
__device__ __half g_W1sT[256 * 128];           // [n][k]
__device__ __half g_W1rT[256 * 128];
__device__ __half g_W1eT[256 * 128];
__device__ __half g_W2T[128 * 256];

// ---- main-kernel smem byte offsets ----
#define OF_B1   0        // 256 f
#define OF_B2   1024     // 128 f
#define OF_G    1536     // 128 f
#define OF_BT   2048     // 128 f
#define OF_SI   2560     // 128 i
#define OF_RI   3072     // 128 i
#define OF_W1E  3584     // 256*136 half = 69632
#define OF_W2R  73216    // 128*264 half = 67584
#define OF_H    140800   // 128*264 half = 67584 (X bufs + fp32 LN scratch live here too)
#define SMEM_BYTES 208384

// ---- precompute-kernel smem ----
#define PF_X0  0
#define PF_X1  10240
#define PF_W0  20480
#define PF_W1B 40960
#define SMEM_PRE (PF_W1B + 20480)

#define XS  40    // X chunk row stride (half)
#define W1S 136   // resident W1e row stride (half)
#define W2S 264   // resident W2 row stride (half)
#define WS  40    // precompute panel stride
#define HS  264
#define OS  132

__device__ __forceinline__ uint32_t smem_u32(const void* p) {
    uint32_t a;
    asm("{ .reg .u64 t; cvta.to.shared.u64 t, %1; cvt.u32.u64 %0, t; }" : "=r"(a) : "l"(p));
    return a;
}
__device__ __forceinline__ uint32_t pkh2(float lo, float hi) {
    uint32_t r; asm("cvt.rn.f16x2.f32 %0, %1, %2;" : "=r"(r) : "f"(hi), "f"(lo)); return r;
}
__device__ __forceinline__ void mma16(float (&d)[4], const uint32_t (&a)[4],
                                      uint32_t b0, uint32_t b1) {
    asm volatile("mma.sync.aligned.m16n8k16.row.col.f32.f16.f16.f32 "
        "{%0,%1,%2,%3}, {%4,%5,%6,%7}, {%8,%9}, {%0,%1,%2,%3};"
        : "+f"(d[0]), "+f"(d[1]), "+f"(d[2]), "+f"(d[3])
        : "r"(a[0]), "r"(a[1]), "r"(a[2]), "r"(a[3]), "r"(b0), "r"(b1));
}
__device__ __forceinline__ void ldsm4(uint32_t (&r)[4], uint32_t addr) {
    asm volatile("ldmatrix.sync.aligned.m8n8.x4.shared.b16 {%0,%1,%2,%3}, [%4];"
        : "=r"(r[0]), "=r"(r[1]), "=r"(r[2]), "=r"(r[3]) : "r"(addr));
}
#define CP16(dst, src) asm volatile("cp.async.ca.shared.global [%0], [%1], 16;" :: "r"(dst), "l"(src) : "memory")
#define CP_COMMIT()    asm volatile("cp.async.commit_group;" ::: "memory")
#define CP_WAIT0()     asm volatile("cp.async.wait_group 0;" ::: "memory")
#define STSV4(a, v)    asm volatile("st.shared.v4.b32 [%0], {%1,%2,%3,%4};" :: "r"(a), "r"((v).x), "r"((v).y), "r"((v).z), "r"((v).w) : "memory")

// ---------------- cvt: node->fp16, W1 split+transpose, W2 transpose ----------------
__global__ void cvt_all_kernel(const float* __restrict__ node,
                               const float* __restrict__ W1,
                               const float* __restrict__ W2) {
    const int NODE8 = N_NODES * 128 / 8;
    const int WTOT  = 4 * 32768;
    for (int i = blockIdx.x * blockDim.x + threadIdx.x; i < NODE8 + WTOT;
         i += gridDim.x * blockDim.x) {
        if (i < NODE8) {
            float4 a = *(const float4*)(node + 8 * (size_t)i);
            float4 b = *(const float4*)(node + 8 * (size_t)i + 4);
            uint4 o;
            o.x = pkh2(a.x, a.y); o.y = pkh2(a.z, a.w);
            o.z = pkh2(b.x, b.y); o.w = pkh2(b.z, b.w);
            *(uint4*)(g_nodeH + 8 * (size_t)i) = o;
        } else {
            int j = i - NODE8;
            if (j < 3 * 32768) {
                int sec = j >> 15, m = j & 32767;
                int n = m >> 7, k = m & 127;
                float v = W1[(sec * 128 + k) * 256 + n];
                __half* dst = (sec == 0) ? g_W1sT : (sec == 1) ? g_W1rT : g_W1eT;
                dst[m] = __float2half_rn(v);
            } else {
                int m = j - 3 * 32768;
                int n = m >> 8, k = m & 255;
                g_W2T[m] = __float2half_rn(W2[k * 128 + n]);
            }
        }
    }
}

// ---------------- precompute: P[n] = node[n] @ [W1s | W1r], PERMUTED cols ----------------
__global__ __launch_bounds__(512, 1)
void precompute_kernel()
{
    extern __shared__ char smem[];
    const int tid = threadIdx.x;
    const int wid = tid >> 5, lane = tid & 31;
    const int lr = lane >> 2, lc = lane & 3;
    const int wm = wid >> 2, wn = wid & 3;
    const int n0 = blockIdx.x * 128;
    const __half* WT = blockIdx.y ? g_W1rT : g_W1sT;

    const int r = tid >> 2, q = tid & 3;
    const __half* pA = g_nodeH + (size_t)(n0 + r) * 128 + q * 8;
    const __half* pW = WT + (size_t)(tid >> 1) * 128 + (tid & 1) * 16;

    const uint32_t sbX[2] = { smem_u32(smem + PF_X0), smem_u32(smem + PF_X1) };
    const uint32_t sbW[2] = { smem_u32(smem + PF_W0), smem_u32(smem + PF_W1B) };
    const uint32_t dX = (uint32_t)(r * XS + q * 8) * 2;
    const uint32_t dW = (uint32_t)((tid >> 1) * WS + (tid & 1) * 16) * 2;

    const int aoff_row = lane & 15;
    const int aoff_k   = (lane >> 4) << 3;
    const int boff_n   = ((lane >> 4) << 3) + (lane & 7);
    const int boff_k   = ((lane >> 3) & 1) << 3;

    CP16(sbX[0] + dX, pA);
    CP16(sbW[0] + dW,      pW);
    CP16(sbW[0] + dW + 16, pW + 8);
    CP_COMMIT(); CP_WAIT0();
    __syncthreads();

    float acc[2][8][4];
    #pragma unroll
    for (int i = 0; i < 2; i++)
        #pragma unroll
        for (int j = 0; j < 8; j++)
            #pragma unroll
            for (int qq = 0; qq < 4; qq++) acc[i][j][qq] = 0.f;

    for (int c = 0; c < 4; c++) {
        if (c < 3) {
            CP16(sbX[(c + 1) & 1] + dX, pA + (c + 1) * 32);
            CP16(sbW[(c + 1) & 1] + dW,      pW + (c + 1) * 32);
            CP16(sbW[(c + 1) & 1] + dW + 16, pW + (c + 1) * 32 + 8);
            CP_COMMIT();
        }
        const uint32_t xb = sbX[c & 1], wb = sbW[c & 1];
        #pragma unroll
        for (int ks = 0; ks < 2; ks++) {
            uint32_t A[2][4];
            #pragma unroll
            for (int i = 0; i < 2; i++)
                ldsm4(A[i], xb + (uint32_t)((wm * 32 + i * 16 + aoff_row) * XS + ks * 16 + aoff_k) * 2);
            #pragma unroll
            for (int jp = 0; jp < 4; jp++) {
                uint32_t B[4];
                ldsm4(B, wb + (uint32_t)((wn * 64 + jp * 16 + boff_n) * WS + ks * 16 + boff_k) * 2);
                mma16(acc[0][2 * jp],     A[0], B[0], B[1]);
                mma16(acc[1][2 * jp],     A[1], B[0], B[1]);
                mma16(acc[0][2 * jp + 1], A[0], B[2], B[3]);
                mma16(acc[1][2 * jp + 1], A[1], B[2], B[3]);
            }
        }
        if (c < 3) CP_WAIT0();
        __syncthreads();
    }

    // permuted store: pair for (j) goes to offset g*64 + 16*lc + 2*j
    const int cbase = blockIdx.y * 256;
    const int poff = wn * 64 + 16 * lc;
    #pragma unroll
    for (int i = 0; i < 2; i++) {
        int row = n0 + wm * 32 + i * 16 + lr;
        #pragma unroll
        for (int j = 0; j < 8; j++) {
            if (row < N_NODES)
                *(uint32_t*)(g_P + (size_t)row * 512 + cbase + poff + 2 * j) =
                    pkh2(acc[i][j][0], acc[i][j][1]);
            if (row + 8 < N_NODES)
                *(uint32_t*)(g_P + (size_t)(row + 8) * 512 + cbase + poff + 2 * j) =
                    pkh2(acc[i][j][2], acc[i][j][3]);
        }
    }
}

// ---------------- main kernel: resident weights, permuted P gather ----------------
__global__ __launch_bounds__(NTH, 1)
void edge_mlp_h(const float* __restrict__ edge_attr,
                const int*   __restrict__ eidx,
                const float* __restrict__ b1,
                const float* __restrict__ b2,
                const float* __restrict__ gamma,
                const float* __restrict__ beta,
                float* __restrict__ out)
{
    extern __shared__ char smem[];
    float* smf = (float*)smem;
    const int tid = threadIdx.x;
    const int wid = tid >> 5, lane = tid & 31;
    const int lr = lane >> 2, lc = lane & 3;
    const int wm = wid >> 2, wn = wid & 3;
    const int e0 = blockIdx.x * TILE_M;

    if (tid < 256) smf[OF_B1 / 4 + tid] = b1[tid];
    if (tid < 128) {
        smf[OF_B2 / 4 + tid] = b2[tid];
        smf[OF_G  / 4 + tid] = gamma[tid];
        smf[OF_BT / 4 + tid] = beta[tid];
        int e = e0 + tid;
        bool ok = e < E_TOT;
        ((int*)(smem + OF_SI))[tid] = ok ? eidx[e] : 0;
        ((int*)(smem + OF_RI))[tid] = ok ? eidx[E_TOT + e] : 0;
    }

    const int r = tid >> 2, q = tid & 3;
    int eMine = e0 + r; if (eMine >= E_TOT) eMine = e0;
    const float* pE = edge_attr + (size_t)eMine * 128 + q * 8;

    const uint32_t sbW1 = smem_u32(smem + OF_W1E);
    const uint32_t sbW2 = smem_u32(smem + OF_W2R);
    const uint32_t sbH  = smem_u32(smem + OF_H);
    const uint32_t sbX[2] = { sbH, sbH + 10240 };
    const uint32_t dX = (uint32_t)(r * XS + q * 8) * 2;

    const int aoff_row = lane & 15;
    const int aoff_k   = (lane >> 4) << 3;
    const int boff_n   = ((lane >> 4) << 3) + (lane & 7);
    const int boff_k   = ((lane >> 3) & 1) << 3;

    // ---- prologue: resident weight preload + X chunk 0 ----
    {
        int n = tid >> 1, h = tid & 1;            // W1e: 256 rows x 2 halves
        const __half* s1 = g_W1eT + (size_t)n * 128 + h * 64;
        uint32_t d1 = sbW1 + (uint32_t)(n * W1S + h * 64) * 2;
        #pragma unroll
        for (int s = 0; s < 8; s++) CP16(d1 + 16 * s, s1 + 8 * s);
        int rw = tid >> 2, qw = tid & 3;          // W2: 128 rows x 4 quarters
        const __half* s2 = g_W2T + (size_t)rw * 256 + qw * 64;
        uint32_t d2 = sbW2 + (uint32_t)(rw * W2S + qw * 64) * 2;
        #pragma unroll
        for (int s = 0; s < 8; s++) CP16(d2 + 16 * s, s2 + 8 * s);
        CP_COMMIT();
        float4 e0v = *(const float4*)pE;
        float4 e1v = *(const float4*)(pE + 4);
        uint4 o;
        o.x = pkh2(e0v.x, e0v.y); o.y = pkh2(e0v.z, e0v.w);
        o.z = pkh2(e1v.x, e1v.y); o.w = pkh2(e1v.z, e1v.w);
        STSV4(sbX[0] + dX, o);
        CP_WAIT0();
    }
    __syncthreads();

    // ======== GEMM1e: accE[128x256] = E[128x128] @ W1e (resident) ========
    float acc[2][8][4];
    #pragma unroll
    for (int i = 0; i < 2; i++)
        #pragma unroll
        for (int j = 0; j < 8; j++)
            #pragma unroll
            for (int qq = 0; qq < 4; qq++) acc[i][j][qq] = 0.f;

    for (int c = 0; c < 4; c++) {
        const bool pre = c < 3;
        float4 ev0, ev1;
        if (pre) {
            const float* src = pE + (c + 1) * 32;
            ev0 = *(const float4*)src;
            ev1 = *(const float4*)(src + 4);
        }
        const uint32_t xb = sbX[c & 1];
        #pragma unroll
        for (int ks = 0; ks < 2; ks++) {
            uint32_t A[2][4];
            #pragma unroll
            for (int i = 0; i < 2; i++)
                ldsm4(A[i], xb + (uint32_t)((wm * 32 + i * 16 + aoff_row) * XS + ks * 16 + aoff_k) * 2);
            #pragma unroll
            for (int jp = 0; jp < 4; jp++) {
                uint32_t B[4];
                ldsm4(B, sbW1 + (uint32_t)((wn * 64 + jp * 16 + boff_n) * W1S + c * 32 + ks * 16 + boff_k) * 2);
                mma16(acc[0][2 * jp],     A[0], B[0], B[1]);
                mma16(acc[1][2 * jp],     A[1], B[0], B[1]);
                mma16(acc[0][2 * jp + 1], A[0], B[2], B[3]);
                mma16(acc[1][2 * jp + 1], A[1], B[2], B[3]);
            }
        }
        if (pre) {
            uint4 o;
            o.x = pkh2(ev0.x, ev0.y); o.y = pkh2(ev0.z, ev0.w);
            o.z = pkh2(ev1.x, ev1.y); o.w = pkh2(ev1.z, ev1.w);
            STSV4(sbX[(c + 1) & 1] + dX, o);
        }
        __syncthreads();
    }

    // ======== epilogue 1: H = fp16(relu(accE + Ps + Pr + b1)), permuted P via LDG.128 ========
    {
        __half* Hh = (__half*)(smem + OF_H);
        const int* sI = (const int*)(smem + OF_SI);
        const int* rI = (const int*)(smem + OF_RI);
        const int pbase = wn * 64 + 16 * lc;
        #pragma unroll
        for (int i = 0; i < 2; i++) {
            int r0 = wm * 32 + i * 16 + lr;
            #pragma unroll
            for (int half = 0; half < 2; half++) {
                int row = r0 + 8 * half;
                const __half* Pse = g_P + (size_t)sI[row] * 512 + pbase;
                const __half* Pre = g_P + (size_t)rI[row] * 512 + 256 + pbase;
                uint4 s0 = *(const uint4*)Pse;
                uint4 s1 = *(const uint4*)(Pse + 8);
                uint4 t0 = *(const uint4*)Pre;
                uint4 t1 = *(const uint4*)(Pre + 8);
                const __half2* sp0 = (const __half2*)&s0;
                const __half2* sp1 = (const __half2*)&s1;
                const __half2* tp0 = (const __half2*)&t0;
                const __half2* tp1 = (const __half2*)&t1;
                #pragma unroll
                for (int j = 0; j < 8; j++) {
                    int col = wn * 64 + j * 8 + 2 * lc;
                    float2 ps = __half22float2(j < 4 ? sp0[j] : sp1[j - 4]);
                    float2 pr = __half22float2(j < 4 ? tp0[j] : tp1[j - 4]);
                    float g0 = smf[OF_B1 / 4 + col], g1 = smf[OF_B1 / 4 + col + 1];
                    *(uint32_t*)(Hh + row * HS + col) =
                        pkh2(fmaxf(acc[i][j][2 * half]     + ps.x + pr.x + g0, 0.f),
                             fmaxf(acc[i][j][2 * half + 1] + ps.y + pr.y + g1, 0.f));
                }
            }
        }
    }
    __syncthreads();

    // ======== GEMM2: C2[128x128] = H[128x256] @ W2 (resident, sync-free) ========
    float acc2[2][4][4];
    #pragma unroll
    for (int i = 0; i < 2; i++)
        #pragma unroll
        for (int j = 0; j < 4; j++)
            #pragma unroll
            for (int qq = 0; qq < 4; qq++) acc2[i][j][qq] = 0.f;

    #pragma unroll
    for (int c = 0; c < 8; c++) {
        #pragma unroll
        for (int ks = 0; ks < 2; ks++) {
            uint32_t A[2][4];
            #pragma unroll
            for (int i = 0; i < 2; i++)
                ldsm4(A[i], sbH + (uint32_t)((wm * 32 + i * 16 + aoff_row) * HS + c * 32 + ks * 16 + aoff_k) * 2);
            #pragma unroll
            for (int jp = 0; jp < 2; jp++) {
                uint32_t B[4];
                ldsm4(B, sbW2 + (uint32_t)((wn * 32 + jp * 16 + boff_n) * W2S + c * 32 + ks * 16 + boff_k) * 2);
                mma16(acc2[0][2 * jp],     A[0], B[0], B[1]);
                mma16(acc2[1][2 * jp],     A[1], B[0], B[1]);
                mma16(acc2[0][2 * jp + 1], A[0], B[2], B[3]);
                mma16(acc2[1][2 * jp + 1], A[1], B[2], B[3]);
            }
        }
    }
    __syncthreads();   // all H reads done before Of overwrites the region

    // ======== epilogue 2: Of = C2 + b2 (smem, fp32) ; LayerNorm -> out ========
    {
        float* Of = (float*)(smem + OF_H);
        #pragma unroll
        for (int i = 0; i < 2; i++) {
            int r0 = wm * 32 + i * 16 + lr;
            #pragma unroll
            for (int j = 0; j < 4; j++) {
                int col = wn * 32 + j * 8 + 2 * lc;
                float g0 = smf[OF_B2 / 4 + col], g1 = smf[OF_B2 / 4 + col + 1];
                Of[r0 * OS + col]           = acc2[i][j][0] + g0;
                Of[r0 * OS + col + 1]       = acc2[i][j][1] + g1;
                Of[(r0 + 8) * OS + col]     = acc2[i][j][2] + g0;
                Of[(r0 + 8) * OS + col + 1] = acc2[i][j][3] + g1;
            }
        }
    }
    __syncthreads();
    {
        const float* Of = (const float*)(smem + OF_H);
        float4 ga = *(const float4*)(smf + OF_G  / 4 + 4 * lane);
        float4 bt = *(const float4*)(smf + OF_BT / 4 + 4 * lane);
        #pragma unroll
        for (int rr = 0; rr < 8; rr++) {
            int row = wid * 8 + rr;
            int e = e0 + row;
            float4 v = *(const float4*)(Of + row * OS + 4 * lane);
            float s = v.x + v.y + v.z + v.w;
            float qs = v.x * v.x + v.y * v.y + v.z * v.z + v.w * v.w;
            #pragma unroll
            for (int o = 16; o > 0; o >>= 1) {
                s  += __shfl_xor_sync(0xffffffffu, s, o);
                qs += __shfl_xor_sync(0xffffffffu, qs, o);
            }
            float mean = s * (1.0f / 128.0f);
            float var  = qs * (1.0f / 128.0f) - mean * mean;
            float inv  = rsqrtf(var + 1e-5f);
            if (e < E_TOT) {
                float4 o4;
                o4.x = (v.x - mean) * inv * ga.x + bt.x;
                o4.y = (v.y - mean) * inv * ga.y + bt.y;
                o4.z = (v.z - mean) * inv * ga.z + bt.z;
                o4.w = (v.w - mean) * inv * ga.w + bt.w;
                *(float4*)(out + (size_t)e * 128 + 4 * lane) = o4;
            }
        }
    }
}

extern "C" void kernel_launch(void* const* d_in, const int* in_sizes, int n_in,
                              void* d_out, int out_size)
{
    (void)in_sizes; (void)n_in; (void)out_size;
    cvt_all_kernel<<<2048, 256>>>((const float*)d_in[0],
                                  (const float*)d_in[3],
                                  (const float*)d_in[5]);
    cudaFuncSetAttribute(precompute_kernel,
                         cudaFuncAttributeMaxDynamicSharedMemorySize, SMEM_PRE);
    precompute_kernel<<<dim3((N_NODES + 127) / 128, 2), 512, SMEM_PRE>>>();
    cudaFuncSetAttribute(edge_mlp_h,
                         cudaFuncAttributeMaxDynamicSharedMemorySize, SMEM_BYTES);
    dim3 grid((E_TOT + TILE_M - 1) / TILE_M);
    edge_mlp_h<<<grid, NTH, SMEM_BYTES>>>(
        (const float*)d_in[1],   // edge_contact_attr
        (const int*)  d_in[2],   // edge_contact_index
        (const float*)d_in[4],   // b1
        (const float*)d_in[6],   // b2
        (const float*)d_in[7],   // ln_gamma
        (const float*)d_in[8],   // ln_beta
        (float*)d_out);
}

// round 12
// speedup vs baseline: 1.0205x; 1.0008x over previous
#include <cuda_runtime.h>
#include <cuda_fp16.h>
#include <cstdint>

#define E_TOT   300000
#define N_NODES 50000
#define NPAD    (N_NODES + 128)
#define TILE_M  128
#define NTH     512

__device__ __half g_nodeH[(size_t)NPAD * 128];
__device__ __half g_P[(size_t)NPAD * 512];     // [node][ Ps(256 perm) | Pr(256 perm) ]
__device__ __half g_W1sT[256 * 128];           // [n][k]
__device__ __half g_W1rT[256 * 128];
__device__ __half g_W1eT[256 * 128];
__device__ __half g_W2T[128 * 256];

// ---- main-kernel smem byte offsets ----
#define OF_B1   0        // 256 f
#define OF_B2   1024     // 128 f
#define OF_G    1536     // 128 f
#define OF_BT   2048     // 128 f
#define OF_SI   2560     // 128 i
#define OF_RI   3072     // 128 i
#define OF_W1E  3584     // 256*136 half = 69632
#define OF_W2R  73216    // 128*264 half = 67584
#define OF_H    140800   // 128*264 half = 67584 (X bufs + fp32 LN scratch live here too)
#define SMEM_BYTES 208384

// ---- precompute-kernel smem ----
#define PF_X0  0
#define PF_X1  10240
#define PF_W0  20480
#define PF_W1B 40960
#define SMEM_PRE (PF_W1B + 20480)

#define XS  40    // X chunk row stride (half)
#define W1S 136   // resident W1e row stride (half)
#define W2S 264   // resident W2 row stride (half)
#define WS  40    // precompute panel stride
#define HS  264
#define OS  132

__device__ __forceinline__ uint32_t smem_u32(const void* p) {
    uint32_t a;
    asm("{ .reg .u64 t; cvta.to.shared.u64 t, %1; cvt.u32.u64 %0, t; }" : "=r"(a) : "l"(p));
    return a;
}
__device__ __forceinline__ uint32_t pkh2(float lo, float hi) {
    uint32_t r; asm("cvt.rn.f16x2.f32 %0, %1, %2;" : "=r"(r) : "f"(hi), "f"(lo)); return r;
}
__device__ __forceinline__ void mma16(float (&d)[4], const uint32_t (&a)[4],
                                      uint32_t b0, uint32_t b1) {
    asm volatile("mma.sync.aligned.m16n8k16.row.col.f32.f16.f16.f32 "
        "{%0,%1,%2,%3}, {%4,%5,%6,%7}, {%8,%9}, {%0,%1,%2,%3};"
        : "+f"(d[0]), "+f"(d[1]), "+f"(d[2]), "+f"(d[3])
        : "r"(a[0]), "r"(a[1]), "r"(a[2]), "r"(a[3]), "r"(b0), "r"(b1));
}
__device__ __forceinline__ void ldsm4(uint32_t (&r)[4], uint32_t addr) {
    asm volatile("ldmatrix.sync.aligned.m8n8.x4.shared.b16 {%0,%1,%2,%3}, [%4];"
        : "=r"(r[0]), "=r"(r[1]), "=r"(r[2]), "=r"(r[3]) : "r"(addr));
}
#define CP16(dst, src) asm volatile("cp.async.ca.shared.global [%0], [%1], 16;" :: "r"(dst), "l"(src) : "memory")
#define CP_COMMIT()    asm volatile("cp.async.commit_group;" ::: "memory")
#define CP_WAIT0()     asm volatile("cp.async.wait_group 0;" ::: "memory")
#define STSV4(a, v)    asm volatile("st.shared.v4.b32 [%0], {%1,%2,%3,%4};" :: "r"(a), "r"((v).x), "r"((v).y), "r"((v).z), "r"((v).w) : "memory")

// ---------------- cvt: node->fp16, W1 split+transpose, W2 transpose ----------------
__global__ void cvt_all_kernel(const float* __restrict__ node,
                               const float* __restrict__ W1,
                               const float* __restrict__ W2) {
    const int NODE8 = N_NODES * 128 / 8;
    const int WTOT  = 4 * 32768;
    for (int i = blockIdx.x * blockDim.x + threadIdx.x; i < NODE8 + WTOT;
         i += gridDim.x * blockDim.x) {
        if (i < NODE8) {
            float4 a = *(const float4*)(node + 8 * (size_t)i);
            float4 b = *(const float4*)(node + 8 * (size_t)i + 4);
            uint4 o;
            o.x = pkh2(a.x, a.y); o.y = pkh2(a.z, a.w);
            o.z = pkh2(b.x, b.y); o.w = pkh2(b.z, b.w);
            *(uint4*)(g_nodeH + 8 * (size_t)i) = o;
        } else {
            int j = i - NODE8;
            if (j < 3 * 32768) {
                int sec = j >> 15, m = j & 32767;
                int n = m >> 7, k = m & 127;
                float v = W1[(sec * 128 + k) * 256 + n];
                __half* dst = (sec == 0) ? g_W1sT : (sec == 1) ? g_W1rT : g_W1eT;
                dst[m] = __float2half_rn(v);
            } else {
                int m = j - 3 * 32768;
                int n = m >> 8, k = m & 255;
                g_W2T[m] = __float2half_rn(W2[k * 128 + n]);
            }
        }
    }
}

// ---------------- precompute: P[n] = node[n] @ [W1s | W1r], PERMUTED cols ----------------
__global__ __launch_bounds__(512, 1)
void precompute_kernel()
{
    extern __shared__ char smem[];
    const int tid = threadIdx.x;
    const int wid = tid >> 5, lane = tid & 31;
    const int lr = lane >> 2, lc = lane & 3;
    const int wm = wid >> 2, wn = wid & 3;
    const int n0 = blockIdx.x * 128;
    const __half* WT = blockIdx.y ? g_W1rT : g_W1sT;

    const int r = tid >> 2, q = tid & 3;
    const __half* pA = g_nodeH + (size_t)(n0 + r) * 128 + q * 8;
    const __half* pW = WT + (size_t)(tid >> 1) * 128 + (tid & 1) * 16;

    const uint32_t sbX[2] = { smem_u32(smem + PF_X0), smem_u32(smem + PF_X1) };
    const uint32_t sbW[2] = { smem_u32(smem + PF_W0), smem_u32(smem + PF_W1B) };
    const uint32_t dX = (uint32_t)(r * XS + q * 8) * 2;
    const uint32_t dW = (uint32_t)((tid >> 1) * WS + (tid & 1) * 16) * 2;

    const int aoff_row = lane & 15;
    const int aoff_k   = (lane >> 4) << 3;
    const int boff_n   = ((lane >> 4) << 3) + (lane & 7);
    const int boff_k   = ((lane >> 3) & 1) << 3;

    CP16(sbX[0] + dX, pA);
    CP16(sbW[0] + dW,      pW);
    CP16(sbW[0] + dW + 16, pW + 8);
    CP_COMMIT(); CP_WAIT0();
    __syncthreads();

    float acc[2][8][4];
    #pragma unroll
    for (int i = 0; i < 2; i++)
        #pragma unroll
        for (int j = 0; j < 8; j++)
            #pragma unroll
            for (int qq = 0; qq < 4; qq++) acc[i][j][qq] = 0.f;

    for (int c = 0; c < 4; c++) {
        if (c < 3) {
            CP16(sbX[(c + 1) & 1] + dX, pA + (c + 1) * 32);
            CP16(sbW[(c + 1) & 1] + dW,      pW + (c + 1) * 32);
            CP16(sbW[(c + 1) & 1] + dW + 16, pW + (c + 1) * 32 + 8);
            CP_COMMIT();
        }
        const uint32_t xb = sbX[c & 1], wb = sbW[c & 1];
        #pragma unroll
        for (int ks = 0; ks < 2; ks++) {
            uint32_t A[2][4];
            #pragma unroll
            for (int i = 0; i < 2; i++)
                ldsm4(A[i], xb + (uint32_t)((wm * 32 + i * 16 + aoff_row) * XS + ks * 16 + aoff_k) * 2);
            #pragma unroll
            for (int jp = 0; jp < 4; jp++) {
                uint32_t B[4];
                ldsm4(B, wb + (uint32_t)((wn * 64 + jp * 16 + boff_n) * WS + ks * 16 + boff_k) * 2);
                mma16(acc[0][2 * jp],     A[0], B[0], B[1]);
                mma16(acc[1][2 * jp],     A[1], B[0], B[1]);
                mma16(acc[0][2 * jp + 1], A[0], B[2], B[3]);
                mma16(acc[1][2 * jp + 1], A[1], B[2], B[3]);
            }
        }
        if (c < 3) CP_WAIT0();
        __syncthreads();
    }

    // permuted store: pair for (j) goes to offset g*64 + 16*lc + 2*j
    const int cbase = blockIdx.y * 256;
    const int poff = wn * 64 + 16 * lc;
    #pragma unroll
    for (int i = 0; i < 2; i++) {
        int row = n0 + wm * 32 + i * 16 + lr;
        #pragma unroll
        for (int j = 0; j < 8; j++) {
            if (row < N_NODES)
                *(uint32_t*)(g_P + (size_t)row * 512 + cbase + poff + 2 * j) =
                    pkh2(acc[i][j][0], acc[i][j][1]);
            if (row + 8 < N_NODES)
                *(uint32_t*)(g_P + (size_t)(row + 8) * 512 + cbase + poff + 2 * j) =
                    pkh2(acc[i][j][2], acc[i][j][3]);
        }
    }
}

// ---------------- main kernel: resident weights, permuted P gather ----------------
__global__ __launch_bounds__(NTH, 1)
void edge_mlp_h(const float* __restrict__ edge_attr,
                const int*   __restrict__ eidx,
                const float* __restrict__ b1,
                const float* __restrict__ b2,
                const float* __restrict__ gamma,
                const float* __restrict__ beta,
                float* __restrict__ out)
{
    extern __shared__ char smem[];
    float* smf = (float*)smem;
    const int tid = threadIdx.x;
    const int wid = tid >> 5, lane = tid & 31;
    const int lr = lane >> 2, lc = lane & 3;
    const int wm = wid >> 2, wn = wid & 3;
    const int e0 = blockIdx.x * TILE_M;

    if (tid < 256) smf[OF_B1 / 4 + tid] = b1[tid];
    if (tid < 128) {
        smf[OF_B2 / 4 + tid] = b2[tid];
        smf[OF_G  / 4 + tid] = gamma[tid];
        smf[OF_BT / 4 + tid] = beta[tid];
        int e = e0 + tid;
        bool ok = e < E_TOT;
        ((int*)(smem + OF_SI))[tid] = ok ? eidx[e] : 0;
        ((int*)(smem + OF_RI))[tid] = ok ? eidx[E_TOT + e] : 0;
    }

    const int r = tid >> 2, q = tid & 3;
    int eMine = e0 + r; if (eMine >= E_TOT) eMine = e0;
    const float* pE = edge_attr + (size_t)eMine * 128 + q * 8;

    const uint32_t sbW1 = smem_u32(smem + OF_W1E);
    const uint32_t sbW2 = smem_u32(smem + OF_W2R);
    const uint32_t sbH  = smem_u32(smem + OF_H);
    const uint32_t sbX[2] = { sbH, sbH + 10240 };
    const uint32_t dX = (uint32_t)(r * XS + q * 8) * 2;

    const int aoff_row = lane & 15;
    const int aoff_k   = (lane >> 4) << 3;
    const int boff_n   = ((lane >> 4) << 3) + (lane & 7);
    const int boff_k   = ((lane >> 3) & 1) << 3;

    // ---- prologue: resident weight preload + X chunk 0 ----
    {
        int n = tid >> 1, h = tid & 1;            // W1e: 256 rows x 2 halves
        const __half* s1 = g_W1eT + (size_t)n * 128 + h * 64;
        uint32_t d1 = sbW1 + (uint32_t)(n * W1S + h * 64) * 2;
        #pragma unroll
        for (int s = 0; s < 8; s++) CP16(d1 + 16 * s, s1 + 8 * s);
        int rw = tid >> 2, qw = tid & 3;          // W2: 128 rows x 4 quarters
        const __half* s2 = g_W2T + (size_t)rw * 256 + qw * 64;
        uint32_t d2 = sbW2 + (uint32_t)(rw * W2S + qw * 64) * 2;
        #pragma unroll
        for (int s = 0; s < 8; s++) CP16(d2 + 16 * s, s2 + 8 * s);
        CP_COMMIT();
        float4 e0v = *(const float4*)pE;
        float4 e1v = *(const float4*)(pE + 4);
        uint4 o;
        o.x = pkh2(e0v.x, e0v.y); o.y = pkh2(e0v.z, e0v.w);
        o.z = pkh2(e1v.x, e1v.y); o.w = pkh2(e1v.z, e1v.w);
        STSV4(sbX[0] + dX, o);
        CP_WAIT0();
    }
    __syncthreads();

    // ======== GEMM1e: accE[128x256] = E[128x128] @ W1e (resident) ========
    float acc[2][8][4];
    #pragma unroll
    for (int i = 0; i < 2; i++)
        #pragma unroll
        for (int j = 0; j < 8; j++)
            #pragma unroll
            for (int qq = 0; qq < 4; qq++) acc[i][j][qq] = 0.f;

    for (int c = 0; c < 4; c++) {
        const bool pre = c < 3;
        float4 ev0, ev1;
        if (pre) {
            const float* src = pE + (c + 1) * 32;
            ev0 = *(const float4*)src;
            ev1 = *(const float4*)(src + 4);
        }
        const uint32_t xb = sbX[c & 1];
        #pragma unroll
        for (int ks = 0; ks < 2; ks++) {
            uint32_t A[2][4];
            #pragma unroll
            for (int i = 0; i < 2; i++)
                ldsm4(A[i], xb + (uint32_t)((wm * 32 + i * 16 + aoff_row) * XS + ks * 16 + aoff_k) * 2);
            #pragma unroll
            for (int jp = 0; jp < 4; jp++) {
                uint32_t B[4];
                ldsm4(B, sbW1 + (uint32_t)((wn * 64 + jp * 16 + boff_n) * W1S + c * 32 + ks * 16 + boff_k) * 2);
                mma16(acc[0][2 * jp],     A[0], B[0], B[1]);
                mma16(acc[1][2 * jp],     A[1], B[0], B[1]);
                mma16(acc[0][2 * jp + 1], A[0], B[2], B[3]);
                mma16(acc[1][2 * jp + 1], A[1], B[2], B[3]);
            }
        }
        if (pre) {
            uint4 o;
            o.x = pkh2(ev0.x, ev0.y); o.y = pkh2(ev0.z, ev0.w);
            o.z = pkh2(ev1.x, ev1.y); o.w = pkh2(ev1.z, ev1.w);
            STSV4(sbX[(c + 1) & 1] + dX, o);
        }
        __syncthreads();
    }

    // ======== epilogue 1: H = fp16(relu(accE + Ps + Pr + b1)), permuted P via LDG.128 ========
    {
        __half* Hh = (__half*)(smem + OF_H);
        const int* sI = (const int*)(smem + OF_SI);
        const int* rI = (const int*)(smem + OF_RI);
        const int pbase = wn * 64 + 16 * lc;
        #pragma unroll
        for (int i = 0; i < 2; i++) {
            int r0 = wm * 32 + i * 16 + lr;
            #pragma unroll
            for (int half = 0; half < 2; half++) {
                int row = r0 + 8 * half;
                const __half* Pse = g_P + (size_t)sI[row] * 512 + pbase;
                const __half* Pre = g_P + (size_t)rI[row] * 512 + 256 + pbase;
                uint4 s0 = *(const uint4*)Pse;
                uint4 s1 = *(const uint4*)(Pse + 8);
                uint4 t0 = *(const uint4*)Pre;
                uint4 t1 = *(const uint4*)(Pre + 8);
                const __half2* sp0 = (const __half2*)&s0;
                const __half2* sp1 = (const __half2*)&s1;
                const __half2* tp0 = (const __half2*)&t0;
                const __half2* tp1 = (const __half2*)&t1;
                #pragma unroll
                for (int j = 0; j < 8; j++) {
                    int col = wn * 64 + j * 8 + 2 * lc;
                    float2 ps = __half22float2(j < 4 ? sp0[j] : sp1[j - 4]);
                    float2 pr = __half22float2(j < 4 ? tp0[j] : tp1[j - 4]);
                    float g0 = smf[OF_B1 / 4 + col], g1 = smf[OF_B1 / 4 + col + 1];
                    *(uint32_t*)(Hh + row * HS + col) =
                        pkh2(fmaxf(acc[i][j][2 * half]     + ps.x + pr.x + g0, 0.f),
                             fmaxf(acc[i][j][2 * half + 1] + ps.y + pr.y + g1, 0.f));
                }
            }
        }
    }
    __syncthreads();

    // ======== GEMM2: C2[128x128] = H[128x256] @ W2 (resident, sync-free) ========
    float acc2[2][4][4];
    #pragma unroll
    for (int i = 0; i < 2; i++)
        #pragma unroll
        for (int j = 0; j < 4; j++)
            #pragma unroll
            for (int qq = 0; qq < 4; qq++) acc2[i][j][qq] = 0.f;

    #pragma unroll
    for (int c = 0; c < 8; c++) {
        #pragma unroll
        for (int ks = 0; ks < 2; ks++) {
            uint32_t A[2][4];
            #pragma unroll
            for (int i = 0; i < 2; i++)
                ldsm4(A[i], sbH + (uint32_t)((wm * 32 + i * 16 + aoff_row) * HS + c * 32 + ks * 16 + aoff_k) * 2);
            #pragma unroll
            for (int jp = 0; jp < 2; jp++) {
                uint32_t B[4];
                ldsm4(B, sbW2 + (uint32_t)((wn * 32 + jp * 16 + boff_n) * W2S + c * 32 + ks * 16 + boff_k) * 2);
                mma16(acc2[0][2 * jp],     A[0], B[0], B[1]);
                mma16(acc2[1][2 * jp],     A[1], B[0], B[1]);
                mma16(acc2[0][2 * jp + 1], A[0], B[2], B[3]);
                mma16(acc2[1][2 * jp + 1], A[1], B[2], B[3]);
            }
        }
    }
    __syncthreads();   // all H reads done before Of overwrites the region

    // ======== epilogue 2: Of = C2 + b2 (smem, fp32) ; LayerNorm -> out ========
    {
        float* Of = (float*)(smem + OF_H);
        #pragma unroll
        for (int i = 0; i < 2; i++) {
            int r0 = wm * 32 + i * 16 + lr;
            #pragma unroll
            for (int j = 0; j < 4; j++) {
                int col = wn * 32 + j * 8 + 2 * lc;
                float g0 = smf[OF_B2 / 4 + col], g1 = smf[OF_B2 / 4 + col + 1];
                Of[r0 * OS + col]           = acc2[i][j][0] + g0;
                Of[r0 * OS + col + 1]       = acc2[i][j][1] + g1;
                Of[(r0 + 8) * OS + col]     = acc2[i][j][2] + g0;
                Of[(r0 + 8) * OS + col + 1] = acc2[i][j][3] + g1;
            }
        }
    }
    __syncthreads();
    {
        const float* Of = (const float*)(smem + OF_H);
        float4 ga = *(const float4*)(smf + OF_G  / 4 + 4 * lane);
        float4 bt = *(const float4*)(smf + OF_BT / 4 + 4 * lane);
        #pragma unroll
        for (int rr = 0; rr < 8; rr++) {
            int row = wid * 8 + rr;
            int e = e0 + row;
            float4 v = *(const float4*)(Of + row * OS + 4 * lane);
            float s = v.x + v.y + v.z + v.w;
            float qs = v.x * v.x + v.y * v.y + v.z * v.z + v.w * v.w;
            #pragma unroll
            for (int o = 16; o > 0; o >>= 1) {
                s  += __shfl_xor_sync(0xffffffffu, s, o);
                qs += __shfl_xor_sync(0xffffffffu, qs, o);
            }
            float mean = s * (1.0f / 128.0f);
            float var  = qs * (1.0f / 128.0f) - mean * mean;
            float inv  = rsqrtf(var + 1e-5f);
            if (e < E_TOT) {
                float4 o4;
                o4.x = (v.x - mean) * inv * ga.x + bt.x;
                o4.y = (v.y - mean) * inv * ga.y + bt.y;
                o4.z = (v.z - mean) * inv * ga.z + bt.z;
                o4.w = (v.w - mean) * inv * ga.w + bt.w;
                *(float4*)(out + (size_t)e * 128 + 4 * lane) = o4;
            }
        }
    }
}

extern "C" void kernel_launch(void* const* d_in, const int* in_sizes, int n_in,
                              void* d_out, int out_size)
{
    (void)in_sizes; (void)n_in; (void)out_size;
    cvt_all_kernel<<<2048, 256>>>((const float*)d_in[0],
                                  (const float*)d_in[3],
                                  (const float*)d_in[5]);
    cudaFuncSetAttribute(precompute_kernel,
                         cudaFuncAttributeMaxDynamicSharedMemorySize, SMEM_PRE);
    precompute_kernel<<<dim3((N_NODES + 127) / 128, 2), 512, SMEM_PRE>>>();
    cudaFuncSetAttribute(edge_mlp_h,
                         cudaFuncAttributeMaxDynamicSharedMemorySize, SMEM_BYTES);
    dim3 grid((E_TOT + TILE_M - 1) / TILE_M);
    edge_mlp_h<<<grid, NTH, SMEM_BYTES>>>(
        (const float*)d_in[1],   // edge_contact_attr
        (const int*)  d_in[2],   // edge_contact_index
        (const float*)d_in[4],   // b1
        (const float*)d_in[6],   // b2
        (const float*)d_in[7],   // ln_gamma
        (const float*)d_in[8],   // ln_beta
        (float*)d_out);
}

// round 13
// speedup vs baseline: 1.1721x; 1.1485x over previous
#include <cuda_runtime.h>
#include <cuda_fp16.h>
#include <cstdint>

#define E_TOT   300000
#define N_NODES 50000
#define NPAD    (N_NODES + 128)
#define TILE_M  128
#define NTH     512

__device__ __half g_nodeH[(size_t)NPAD * 128];
__device__ __half g_P[(size_t)NPAD * 512];     // [node][ Ps(256 perm) | Pr(256 perm) ]
__device__ __half g_W1sT[256 * 128];           // [n][k]
__device__ __half g_W1rT[256 * 128];
__device__ __half g_W1eT[256 * 128];
__device__ __half g_W2T[128 * 256];

// ---- smem byte offsets (same as R7) ----
#define OF_B1  0         // 256 f
#define OF_B2  1024      // 128 f
#define OF_G   1536      // 128 f
#define OF_BT  2048      // 128 f
#define OF_SI  2560      // 128 i
#define OF_RI  3072      // 128 i
#define OF_X0  3584      // 128*40 half
#define OF_X1  13824
#define OF_W0  24064     // 256*40 half
#define OF_W1B 44544
#define OF_H   65024     // 128*264 half (reused as float scratch 128*132)
#define SMEM_BYTES (OF_H + 128*264*2)       // 132608
#define SMEM_PRE   (OF_W1B + 256*40*2)      // 65024 (precompute)

#define XS 40
#define WS 40
#define HS 264
#define OS 132

__device__ __forceinline__ uint32_t smem_u32(const void* p) {
    uint32_t a;
    asm("{ .reg .u64 t; cvta.to.shared.u64 t, %1; cvt.u32.u64 %0, t; }" : "=r"(a) : "l"(p));
    return a;
}
__device__ __forceinline__ uint32_t pkh2(float lo, float hi) {
    uint32_t r; asm("cvt.rn.f16x2.f32 %0, %1, %2;" : "=r"(r) : "f"(hi), "f"(lo)); return r;
}
__device__ __forceinline__ void mma16(float (&d)[4], const uint32_t (&a)[4],
                                      uint32_t b0, uint32_t b1) {
    asm volatile("mma.sync.aligned.m16n8k16.row.col.f32.f16.f16.f32 "
        "{%0,%1,%2,%3}, {%4,%5,%6,%7}, {%8,%9}, {%0,%1,%2,%3};"
        : "+f"(d[0]), "+f"(d[1]), "+f"(d[2]), "+f"(d[3])
        : "r"(a[0]), "r"(a[1]), "r"(a[2]), "r"(a[3]), "r"(b0), "r"(b1));
}
__device__ __forceinline__ void ldsm4(uint32_t (&r)[4], uint32_t addr) {
    asm volatile("ldmatrix.sync.aligned.m8n8.x4.shared.b16 {%0,%1,%2,%3}, [%4];"
        : "=r"(r[0]), "=r"(r[1]), "=r"(r[2]), "=r"(r[3]) : "r"(addr));
}
#define CP16(dst, src) asm volatile("cp.async.ca.shared.global [%0], [%1], 16;" :: "r"(dst), "l"(src) : "memory")
#define CP_COMMIT()    asm volatile("cp.async.commit_group;" ::: "memory")
#define CP_WAIT0()     asm volatile("cp.async.wait_group 0;" ::: "memory")
#define STSV4(a, v)    asm volatile("st.shared.v4.b32 [%0], {%1,%2,%3,%4};" :: "r"(a), "r"((v).x), "r"((v).y), "r"((v).z), "r"((v).w) : "memory")

// ---------------- cvt: node->fp16, W1 split+transpose, W2 transpose ----------------
__global__ void cvt_all_kernel(const float* __restrict__ node,
                               const float* __restrict__ W1,
                               const float* __restrict__ W2) {
    const int NODE8 = N_NODES * 128 / 8;
    const int WTOT  = 4 * 32768;
    for (int i = blockIdx.x * blockDim.x + threadIdx.x; i < NODE8 + WTOT;
         i += gridDim.x * blockDim.x) {
        if (i < NODE8) {
            float4 a = *(const float4*)(node + 8 * (size_t)i);
            float4 b = *(const float4*)(node + 8 * (size_t)i + 4);
            uint4 o;
            o.x = pkh2(a.x, a.y); o.y = pkh2(a.z, a.w);
            o.z = pkh2(b.x, b.y); o.w = pkh2(b.z, b.w);
            *(uint4*)(g_nodeH + 8 * (size_t)i) = o;
        } else {
            int j = i - NODE8;
            if (j < 3 * 32768) {
                int sec = j >> 15, m = j & 32767;
                int n = m >> 7, k = m & 127;
                float v = W1[(sec * 128 + k) * 256 + n];
                __half* dst = (sec == 0) ? g_W1sT : (sec == 1) ? g_W1rT : g_W1eT;
                dst[m] = __float2half_rn(v);
            } else {
                int m = j - 3 * 32768;
                int n = m >> 8, k = m & 255;
                g_W2T[m] = __float2half_rn(W2[k * 128 + n]);
            }
        }
    }
}

// ---------------- precompute: P[n] = node[n] @ [W1s | W1r], PERMUTED cols ----------------
__global__ __launch_bounds__(512, 1)
void precompute_kernel()
{
    extern __shared__ char smem[];
    const int tid = threadIdx.x;
    const int wid = tid >> 5, lane = tid & 31;
    const int lr = lane >> 2, lc = lane & 3;
    const int wm = wid >> 2, wn = wid & 3;
    const int n0 = blockIdx.x * 128;
    const __half* WT = blockIdx.y ? g_W1rT : g_W1sT;

    const int r = tid >> 2, q = tid & 3;
    const __half* pA = g_nodeH + (size_t)(n0 + r) * 128 + q * 8;
    const __half* pW = WT + (size_t)(tid >> 1) * 128 + (tid & 1) * 16;

    const uint32_t sbX[2] = { smem_u32(smem + OF_X0), smem_u32(smem + OF_X1) };
    const uint32_t sbW[2] = { smem_u32(smem + OF_W0), smem_u32(smem + OF_W1B) };
    const uint32_t dX = (uint32_t)(r * XS + q * 8) * 2;
    const uint32_t dW = (uint32_t)((tid >> 1) * WS + (tid & 1) * 16) * 2;

    const int aoff_row = lane & 15;
    const int aoff_k   = (lane >> 4) << 3;
    const int boff_n   = ((lane >> 4) << 3) + (lane & 7);
    const int boff_k   = ((lane >> 3) & 1) << 3;

    CP16(sbX[0] + dX, pA);
    CP16(sbW[0] + dW,      pW);
    CP16(sbW[0] + dW + 16, pW + 8);
    CP_COMMIT(); CP_WAIT0();
    __syncthreads();

    float acc[2][8][4];
    #pragma unroll
    for (int i = 0; i < 2; i++)
        #pragma unroll
        for (int j = 0; j < 8; j++)
            #pragma unroll
            for (int qq = 0; qq < 4; qq++) acc[i][j][qq] = 0.f;

    for (int c = 0; c < 4; c++) {
        if (c < 3) {
            CP16(sbX[(c + 1) & 1] + dX, pA + (c + 1) * 32);
            CP16(sbW[(c + 1) & 1] + dW,      pW + (c + 1) * 32);
            CP16(sbW[(c + 1) & 1] + dW + 16, pW + (c + 1) * 32 + 8);
            CP_COMMIT();
        }
        const uint32_t xb = sbX[c & 1], wb = sbW[c & 1];
        #pragma unroll
        for (int ks = 0; ks < 2; ks++) {
            uint32_t A[2][4];
            #pragma unroll
            for (int i = 0; i < 2; i++)
                ldsm4(A[i], xb + (uint32_t)((wm * 32 + i * 16 + aoff_row) * XS + ks * 16 + aoff_k) * 2);
            #pragma unroll
            for (int jp = 0; jp < 4; jp++) {
                uint32_t B[4];
                ldsm4(B, wb + (uint32_t)((wn * 64 + jp * 16 + boff_n) * WS + ks * 16 + boff_k) * 2);
                mma16(acc[0][2 * jp],     A[0], B[0], B[1]);
                mma16(acc[1][2 * jp],     A[1], B[0], B[1]);
                mma16(acc[0][2 * jp + 1], A[0], B[2], B[3]);
                mma16(acc[1][2 * jp + 1], A[1], B[2], B[3]);
            }
        }
        if (c < 3) CP_WAIT0();
        __syncthreads();
    }

    // permuted store: pair for column group (wn,j,lc) goes to offset wn*64 + 16*lc + 2*j
    const int cbase = blockIdx.y * 256;
    const int poff = wn * 64 + 16 * lc;
    #pragma unroll
    for (int i = 0; i < 2; i++) {
        int row = n0 + wm * 32 + i * 16 + lr;
        #pragma unroll
        for (int j = 0; j < 8; j++) {
            if (row < N_NODES)
                *(uint32_t*)(g_P + (size_t)row * 512 + cbase + poff + 2 * j) =
                    pkh2(acc[i][j][0], acc[i][j][1]);
            if (row + 8 < N_NODES)
                *(uint32_t*)(g_P + (size_t)(row + 8) * 512 + cbase + poff + 2 * j) =
                    pkh2(acc[i][j][2], acc[i][j][3]);
        }
    }
}

// ---------------- main kernel (R7 structure; only epilogue-1 gather changed) ----------------
__global__ __launch_bounds__(NTH, 1)
void edge_mlp_h(const float* __restrict__ edge_attr,
                const int*   __restrict__ eidx,
                const float* __restrict__ b1,
                const float* __restrict__ b2,
                const float* __restrict__ gamma,
                const float* __restrict__ beta,
                float* __restrict__ out)
{
    extern __shared__ char smem[];
    float* smf = (float*)smem;
    const int tid = threadIdx.x;
    const int wid = tid >> 5, lane = tid & 31;
    const int lr = lane >> 2, lc = lane & 3;
    const int wm = wid >> 2, wn = wid & 3;
    const int e0 = blockIdx.x * TILE_M;

    if (tid < 256) smf[OF_B1 / 4 + tid] = b1[tid];
    if (tid < 128) {
        smf[OF_B2 / 4 + tid] = b2[tid];
        smf[OF_G  / 4 + tid] = gamma[tid];
        smf[OF_BT / 4 + tid] = beta[tid];
        int e = e0 + tid;
        bool ok = e < E_TOT;
        ((int*)(smem + OF_SI))[tid] = ok ? eidx[e] : 0;
        ((int*)(smem + OF_RI))[tid] = ok ? eidx[E_TOT + e] : 0;
    }

    const int r = tid >> 2, q = tid & 3;
    int eMine = e0 + r; if (eMine >= E_TOT) eMine = e0;
    const float*  pE   = edge_attr + (size_t)eMine * 128 + q * 8;
    const __half* pW1e = g_W1eT + (size_t)(tid >> 1) * 128 + (tid & 1) * 16;
    const __half* pW2  = g_W2T + (size_t)r * 256 + q * 8;

    const uint32_t sbX[2] = { smem_u32(smem + OF_X0), smem_u32(smem + OF_X1) };
    const uint32_t sbW[2] = { smem_u32(smem + OF_W0), smem_u32(smem + OF_W1B) };
    const uint32_t sbH    = smem_u32(smem + OF_H);
    const uint32_t dX  = (uint32_t)(r * XS + q * 8) * 2;
    const uint32_t dW1 = (uint32_t)((tid >> 1) * WS + (tid & 1) * 16) * 2;
    const uint32_t dW2 = (uint32_t)(r * WS + q * 8) * 2;

    const int aoff_row = lane & 15;
    const int aoff_k   = (lane >> 4) << 3;
    const int boff_n   = ((lane >> 4) << 3) + (lane & 7);
    const int boff_k   = ((lane >> 3) & 1) << 3;

    // prologue: stage chunk 0 (edge cols 0..31 + W1e panel 0)
    {
        float4 e0v = *(const float4*)pE;
        float4 e1v = *(const float4*)(pE + 4);
        uint4 o;
        o.x = pkh2(e0v.x, e0v.y); o.y = pkh2(e0v.z, e0v.w);
        o.z = pkh2(e1v.x, e1v.y); o.w = pkh2(e1v.z, e1v.w);
        STSV4(sbX[0] + dX, o);
        CP16(sbW[0] + dW1,      pW1e);
        CP16(sbW[0] + dW1 + 16, pW1e + 8);
        CP_COMMIT(); CP_WAIT0();
    }
    __syncthreads();

    // ======== GEMM1e: accE[128x256] = E[128x128] @ W1e ========
    float acc[2][8][4];
    #pragma unroll
    for (int i = 0; i < 2; i++)
        #pragma unroll
        for (int j = 0; j < 8; j++)
            #pragma unroll
            for (int qq = 0; qq < 4; qq++) acc[i][j][qq] = 0.f;

    for (int c = 0; c < 4; c++) {
        const bool pre = c < 3;
        float4 ev0, ev1;
        if (pre) {
            const float* src = pE + (c + 1) * 32;
            ev0 = *(const float4*)src;
            ev1 = *(const float4*)(src + 4);
            CP16(sbW[(c + 1) & 1] + dW1,      pW1e + (c + 1) * 32);
            CP16(sbW[(c + 1) & 1] + dW1 + 16, pW1e + (c + 1) * 32 + 8);
            CP_COMMIT();
        }
        const uint32_t xb = sbX[c & 1], wb = sbW[c & 1];
        #pragma unroll
        for (int ks = 0; ks < 2; ks++) {
            uint32_t A[2][4];
            #pragma unroll
            for (int i = 0; i < 2; i++)
                ldsm4(A[i], xb + (uint32_t)((wm * 32 + i * 16 + aoff_row) * XS + ks * 16 + aoff_k) * 2);
            #pragma unroll
            for (int jp = 0; jp < 4; jp++) {
                uint32_t B[4];
                ldsm4(B, wb + (uint32_t)((wn * 64 + jp * 16 + boff_n) * WS + ks * 16 + boff_k) * 2);
                mma16(acc[0][2 * jp],     A[0], B[0], B[1]);
                mma16(acc[1][2 * jp],     A[1], B[0], B[1]);
                mma16(acc[0][2 * jp + 1], A[0], B[2], B[3]);
                mma16(acc[1][2 * jp + 1], A[1], B[2], B[3]);
            }
        }
        if (pre) {
            uint4 o;
            o.x = pkh2(ev0.x, ev0.y); o.y = pkh2(ev0.z, ev0.w);
            o.z = pkh2(ev1.x, ev1.y); o.w = pkh2(ev1.z, ev1.w);
            STSV4(sbX[(c + 1) & 1] + dX, o);
            CP_WAIT0();
        }
        __syncthreads();
    }

    // ======== epilogue 1: H = fp16(relu(accE + Ps + Pr + b1)), permuted P via LDG.128 ========
    {
        __half* Hh = (__half*)(smem + OF_H);
        const int* sI = (const int*)(smem + OF_SI);
        const int* rI = (const int*)(smem + OF_RI);
        CP16(sbW[0] + dW2, pW2);
        CP_COMMIT();
        const int pbase = wn * 64 + 16 * lc;
        #pragma unroll
        for (int i = 0; i < 2; i++) {
            int r0 = wm * 32 + i * 16 + lr;
            #pragma unroll
            for (int half = 0; half < 2; half++) {
                int row = r0 + 8 * half;
                const __half* Pse = g_P + (size_t)sI[row] * 512 + pbase;
                const __half* Pre = g_P + (size_t)rI[row] * 512 + 256 + pbase;
                uint4 s0 = *(const uint4*)Pse;
                uint4 s1 = *(const uint4*)(Pse + 8);
                uint4 t0 = *(const uint4*)Pre;
                uint4 t1 = *(const uint4*)(Pre + 8);
                const __half2* sp0 = (const __half2*)&s0;
                const __half2* sp1 = (const __half2*)&s1;
                const __half2* tp0 = (const __half2*)&t0;
                const __half2* tp1 = (const __half2*)&t1;
                #pragma unroll
                for (int j = 0; j < 8; j++) {
                    int col = wn * 64 + j * 8 + 2 * lc;
                    float2 ps = __half22float2(j < 4 ? sp0[j] : sp1[j - 4]);
                    float2 pr = __half22float2(j < 4 ? tp0[j] : tp1[j - 4]);
                    float g0 = smf[OF_B1 / 4 + col], g1 = smf[OF_B1 / 4 + col + 1];
                    *(uint32_t*)(Hh + row * HS + col) =
                        pkh2(fmaxf(acc[i][j][2 * half]     + ps.x + pr.x + g0, 0.f),
                             fmaxf(acc[i][j][2 * half + 1] + ps.y + pr.y + g1, 0.f));
                }
            }
        }
        CP_WAIT0();
    }
    __syncthreads();

    // ======== GEMM2: C2[128x128] = H[128x256] @ W2 (streamed panels) ========
    float acc2[2][4][4];
    #pragma unroll
    for (int i = 0; i < 2; i++)
        #pragma unroll
        for (int j = 0; j < 4; j++)
            #pragma unroll
            for (int qq = 0; qq < 4; qq++) acc2[i][j][qq] = 0.f;

    for (int c = 0; c < 8; c++) {
        if (c < 7) {
            CP16(sbW[(c + 1) & 1] + dW2, pW2 + (c + 1) * 32);
            CP_COMMIT();
        }
        const uint32_t wb = sbW[c & 1];
        #pragma unroll
        for (int ks = 0; ks < 2; ks++) {
            uint32_t A[2][4];
            #pragma unroll
            for (int i = 0; i < 2; i++)
                ldsm4(A[i], sbH + (uint32_t)((wm * 32 + i * 16 + aoff_row) * HS + c * 32 + ks * 16 + aoff_k) * 2);
            #pragma unroll
            for (int jp = 0; jp < 2; jp++) {
                uint32_t B[4];
                ldsm4(B, wb + (uint32_t)((wn * 32 + jp * 16 + boff_n) * WS + ks * 16 + boff_k) * 2);
                mma16(acc2[0][2 * jp],     A[0], B[0], B[1]);
                mma16(acc2[1][2 * jp],     A[1], B[0], B[1]);
                mma16(acc2[0][2 * jp + 1], A[0], B[2], B[3]);
                mma16(acc2[1][2 * jp + 1], A[1], B[2], B[3]);
            }
        }
        if (c < 7) CP_WAIT0();
        __syncthreads();
    }

    // ======== epilogue 2: scratch = C2 + b2 ; LayerNorm -> out ========
    {
        float* Of = (float*)(smem + OF_H);
        #pragma unroll
        for (int i = 0; i < 2; i++) {
            int r0 = wm * 32 + i * 16 + lr;
            #pragma unroll
            for (int j = 0; j < 4; j++) {
                int col = wn * 32 + j * 8 + 2 * lc;
                float g0 = smf[OF_B2 / 4 + col], g1 = smf[OF_B2 / 4 + col + 1];
                Of[r0 * OS + col]           = acc2[i][j][0] + g0;
                Of[r0 * OS + col + 1]       = acc2[i][j][1] + g1;
                Of[(r0 + 8) * OS + col]     = acc2[i][j][2] + g0;
                Of[(r0 + 8) * OS + col + 1] = acc2[i][j][3] + g1;
            }
        }
    }
    __syncthreads();
    {
        const float* Of = (const float*)(smem + OF_H);
        float4 ga = *(const float4*)(smf + OF_G  / 4 + 4 * lane);
        float4 bt = *(const float4*)(smf + OF_BT / 4 + 4 * lane);
        #pragma unroll
        for (int rr = 0; rr < 8; rr++) {
            int row = wid * 8 + rr;
            int e = e0 + row;
            float4 v = *(const float4*)(Of + row * OS + 4 * lane);
            float s = v.x + v.y + v.z + v.w;
            float qs = v.x * v.x + v.y * v.y + v.z * v.z + v.w * v.w;
            #pragma unroll
            for (int o = 16; o > 0; o >>= 1) {
                s  += __shfl_xor_sync(0xffffffffu, s, o);
                qs += __shfl_xor_sync(0xffffffffu, qs, o);
            }
            float mean = s * (1.0f / 128.0f);
            float var  = qs * (1.0f / 128.0f) - mean * mean;
            float inv  = rsqrtf(var + 1e-5f);
            if (e < E_TOT) {
                float4 o4;
                o4.x = (v.x - mean) * inv * ga.x + bt.x;
                o4.y = (v.y - mean) * inv * ga.y + bt.y;
                o4.z = (v.z - mean) * inv * ga.z + bt.z;
                o4.w = (v.w - mean) * inv * ga.w + bt.w;
                *(float4*)(out + (size_t)e * 128 + 4 * lane) = o4;
            }
        }
    }
}

extern "C" void kernel_launch(void* const* d_in, const int* in_sizes, int n_in,
                              void* d_out, int out_size)
{
    (void)in_sizes; (void)n_in; (void)out_size;
    cvt_all_kernel<<<2048, 256>>>((const float*)d_in[0],
                                  (const float*)d_in[3],
                                  (const float*)d_in[5]);
    cudaFuncSetAttribute(precompute_kernel,
                         cudaFuncAttributeMaxDynamicSharedMemorySize, SMEM_PRE);
    precompute_kernel<<<dim3((N_NODES + 127) / 128, 2), 512, SMEM_PRE>>>();
    cudaFuncSetAttribute(edge_mlp_h,
                         cudaFuncAttributeMaxDynamicSharedMemorySize, SMEM_BYTES);
    dim3 grid((E_TOT + TILE_M - 1) / TILE_M);
    edge_mlp_h<<<grid, NTH, SMEM_BYTES>>>(
        (const float*)d_in[1],   // edge_contact_attr
        (const int*)  d_in[2],   // edge_contact_index
        (const float*)d_in[4],   // b1
        (const float*)d_in[6],   // b2
        (const float*)d_in[7],   // ln_gamma
        (const float*)d_in[8],   // ln_beta
        (float*)d_out);
}

// round 14
// speedup vs baseline: 1.2213x; 1.0419x over previous
#include <cuda_runtime.h>
#include <cuda_fp16.h>
#include <cstdint>

#define E_TOT   300000
#define N_NODES 50000
#define NPAD    (N_NODES + 128)
#define TILE_M  128
#define NTH     512

__device__ __half g_P[(size_t)NPAD * 512];     // [node][ Ps(256) | Pr(256) ] fp16
__device__ __half g_W1sT[256 * 128];           // [n][k]
__device__ __half g_W1rT[256 * 128];
__device__ __half g_W1eT[256 * 128];
__device__ __half g_W2T[128 * 256];

// ---- main-kernel smem byte offsets ----
#define OF_B1  0         // 256 f
#define OF_B2  1024      // 128 f
#define OF_G   1536      // 128 f
#define OF_BT  2048      // 128 f
#define OF_SI  2560      // 128 i
#define OF_RI  3072      // 128 i
#define OF_X0  3584      // 128*72 half = 18432
#define OF_X1  22016
#define OF_W0  40448     // 256*72 half = 36864
#define OF_W1B 77312
#define OF_H   114176    // 128*264 half = 67584 (reused as float scratch 128*132)
#define SMEM_BYTES 181760

// ---- precompute-kernel smem ----
#define PF_X0  0         // 128*72 half
#define PF_X1  18432
#define PF_W0  36864     // 256*72 half
#define PF_W1B 73728
#define SMEM_PRE 110592

#define XS 72    // X chunk row stride (half), K=64 chunks
#define WS 72    // W panel row stride (half)
#define HS 264
#define OS 132

__device__ __forceinline__ uint32_t smem_u32(const void* p) {
    uint32_t a;
    asm("{ .reg .u64 t; cvta.to.shared.u64 t, %1; cvt.u32.u64 %0, t; }" : "=r"(a) : "l"(p));
    return a;
}
__device__ __forceinline__ uint32_t pkh2(float lo, float hi) {
    uint32_t r; asm("cvt.rn.f16x2.f32 %0, %1, %2;" : "=r"(r) : "f"(hi), "f"(lo)); return r;
}
__device__ __forceinline__ void mma16(float (&d)[4], const uint32_t (&a)[4],
                                      uint32_t b0, uint32_t b1) {
    asm volatile("mma.sync.aligned.m16n8k16.row.col.f32.f16.f16.f32 "
        "{%0,%1,%2,%3}, {%4,%5,%6,%7}, {%8,%9}, {%0,%1,%2,%3};"
        : "+f"(d[0]), "+f"(d[1]), "+f"(d[2]), "+f"(d[3])
        : "r"(a[0]), "r"(a[1]), "r"(a[2]), "r"(a[3]), "r"(b0), "r"(b1));
}
__device__ __forceinline__ void ldsm4(uint32_t (&r)[4], uint32_t addr) {
    asm volatile("ldmatrix.sync.aligned.m8n8.x4.shared.b16 {%0,%1,%2,%3}, [%4];"
        : "=r"(r[0]), "=r"(r[1]), "=r"(r[2]), "=r"(r[3]) : "r"(addr));
}
#define CP16(dst, src) asm volatile("cp.async.ca.shared.global [%0], [%1], 16;" :: "r"(dst), "l"(src) : "memory")
#define CP_COMMIT()    asm volatile("cp.async.commit_group;" ::: "memory")
#define CP_WAIT0()     asm volatile("cp.async.wait_group 0;" ::: "memory")
#define STSV4(a, v)    asm volatile("st.shared.v4.b32 [%0], {%1,%2,%3,%4};" :: "r"(a), "r"((v).x), "r"((v).y), "r"((v).z), "r"((v).w) : "memory")

// convert 16 fp32 (4 float4) -> 2 uint4 of f16x2 and store at smem addr, addr+16
__device__ __forceinline__ void cvt_store32B(uint32_t addr, const float4 fv[4]) {
    uint4 o0, o1;
    o0.x = pkh2(fv[0].x, fv[0].y); o0.y = pkh2(fv[0].z, fv[0].w);
    o0.z = pkh2(fv[1].x, fv[1].y); o0.w = pkh2(fv[1].z, fv[1].w);
    o1.x = pkh2(fv[2].x, fv[2].y); o1.y = pkh2(fv[2].z, fv[2].w);
    o1.z = pkh2(fv[3].x, fv[3].y); o1.w = pkh2(fv[3].z, fv[3].w);
    STSV4(addr, o0);
    STSV4(addr + 16, o1);
}

// ---------------- cvt: weights only (W1 split+transpose, W2 transpose) ----------------
__global__ void cvt_w_kernel(const float* __restrict__ W1,
                             const float* __restrict__ W2) {
    const int WTOT = 4 * 32768;
    for (int j = blockIdx.x * blockDim.x + threadIdx.x; j < WTOT;
         j += gridDim.x * blockDim.x) {
        if (j < 3 * 32768) {
            int sec = j >> 15, m = j & 32767;
            int n = m >> 7, k = m & 127;
            float v = W1[(sec * 128 + k) * 256 + n];
            __half* dst = (sec == 0) ? g_W1sT : (sec == 1) ? g_W1rT : g_W1eT;
            dst[m] = __float2half_rn(v);
        } else {
            int m = j - 3 * 32768;
            int n = m >> 8, k = m & 255;
            g_W2T[m] = __float2half_rn(W2[k * 128 + n]);
        }
    }
}

// ---------------- precompute: P[n] = node[n] @ [W1s | W1r] (fp32 node read) ----------------
__global__ __launch_bounds__(512, 1)
void precompute_kernel(const float* __restrict__ node)
{
    extern __shared__ char smem[];
    const int tid = threadIdx.x;
    const int wid = tid >> 5, lane = tid & 31;
    const int lr = lane >> 2, lc = lane & 3;
    const int wm = wid >> 2, wn = wid & 3;
    const int n0 = blockIdx.x * 128;
    const __half* WT = blockIdx.y ? g_W1rT : g_W1sT;

    const int r = tid >> 2, q = tid & 3;
    int nr = n0 + r; if (nr >= N_NODES) nr = N_NODES - 1;
    const float* pA = node + (size_t)nr * 128 + q * 16;       // + c*64
    const int nw = tid >> 1, hw = tid & 1;
    const __half* pW = WT + (size_t)nw * 128 + hw * 32;       // + c*64

    const uint32_t sbX[2] = { smem_u32(smem + PF_X0), smem_u32(smem + PF_X1) };
    const uint32_t sbW[2] = { smem_u32(smem + PF_W0), smem_u32(smem + PF_W1B) };
    const uint32_t dX = (uint32_t)(r * XS + q * 16) * 2;      // 32B per thread
    const uint32_t dW = (uint32_t)(nw * WS + hw * 32) * 2;    // 64B per thread (4 cp16)

    const int aoff_row = lane & 15;
    const int aoff_k   = (lane >> 4) << 3;
    const int boff_n   = ((lane >> 4) << 3) + (lane & 7);
    const int boff_k   = ((lane >> 3) & 1) << 3;

    // prologue: chunk 0
    {
        #pragma unroll
        for (int s = 0; s < 4; s++) CP16(sbW[0] + dW + 16 * s, pW + 8 * s);
        CP_COMMIT();
        float4 fv[4];
        #pragma unroll
        for (int s = 0; s < 4; s++) fv[s] = *(const float4*)(pA + 4 * s);
        cvt_store32B(sbX[0] + dX, fv);
        CP_WAIT0();
    }
    __syncthreads();

    float acc[2][8][4];
    #pragma unroll
    for (int i = 0; i < 2; i++)
        #pragma unroll
        for (int j = 0; j < 8; j++)
            #pragma unroll
            for (int qq = 0; qq < 4; qq++) acc[i][j][qq] = 0.f;

    for (int c = 0; c < 2; c++) {
        const bool pre = (c == 0);
        float4 fv[4];
        if (pre) {
            #pragma unroll
            for (int s = 0; s < 4; s++) CP16(sbW[1] + dW + 16 * s, pW + 64 + 8 * s);
            CP_COMMIT();
            #pragma unroll
            for (int s = 0; s < 4; s++) fv[s] = *(const float4*)(pA + 64 + 4 * s);
        }
        const uint32_t xb = sbX[c], wb = sbW[c];
        #pragma unroll
        for (int ks = 0; ks < 4; ks++) {
            uint32_t A[2][4];
            #pragma unroll
            for (int i = 0; i < 2; i++)
                ldsm4(A[i], xb + (uint32_t)((wm * 32 + i * 16 + aoff_row) * XS + ks * 16 + aoff_k) * 2);
            #pragma unroll
            for (int jp = 0; jp < 4; jp++) {
                uint32_t B[4];
                ldsm4(B, wb + (uint32_t)((wn * 64 + jp * 16 + boff_n) * WS + ks * 16 + boff_k) * 2);
                mma16(acc[0][2 * jp],     A[0], B[0], B[1]);
                mma16(acc[1][2 * jp],     A[1], B[0], B[1]);
                mma16(acc[0][2 * jp + 1], A[0], B[2], B[3]);
                mma16(acc[1][2 * jp + 1], A[1], B[2], B[3]);
            }
        }
        if (pre) {
            cvt_store32B(sbX[1] + dX, fv);
            CP_WAIT0();
        }
        __syncthreads();
    }

    const int cbase = blockIdx.y * 256;
    #pragma unroll
    for (int i = 0; i < 2; i++) {
        int row = n0 + wm * 32 + i * 16 + lr;
        #pragma unroll
        for (int j = 0; j < 8; j++) {
            int col = wn * 64 + j * 8 + 2 * lc;
            if (row < N_NODES)
                *(uint32_t*)(g_P + (size_t)row * 512 + cbase + col) = pkh2(acc[i][j][0], acc[i][j][1]);
            if (row + 8 < N_NODES)
                *(uint32_t*)(g_P + (size_t)(row + 8) * 512 + cbase + col) = pkh2(acc[i][j][2], acc[i][j][3]);
        }
    }
}

// ---------------- main kernel ----------------
__global__ __launch_bounds__(NTH, 1)
void edge_mlp_h(const float* __restrict__ edge_attr,
                const int*   __restrict__ eidx,
                const float* __restrict__ b1,
                const float* __restrict__ b2,
                const float* __restrict__ gamma,
                const float* __restrict__ beta,
                float* __restrict__ out)
{
    extern __shared__ char smem[];
    float* smf = (float*)smem;
    const int tid = threadIdx.x;
    const int wid = tid >> 5, lane = tid & 31;
    const int lr = lane >> 2, lc = lane & 3;
    const int wm = wid >> 2, wn = wid & 3;
    const int e0 = blockIdx.x * TILE_M;

    if (tid < 256) smf[OF_B1 / 4 + tid] = b1[tid];
    if (tid < 128) {
        smf[OF_B2 / 4 + tid] = b2[tid];
        smf[OF_G  / 4 + tid] = gamma[tid];
        smf[OF_BT / 4 + tid] = beta[tid];
        int e = e0 + tid;
        bool ok = e < E_TOT;
        ((int*)(smem + OF_SI))[tid] = ok ? eidx[e] : 0;
        ((int*)(smem + OF_RI))[tid] = ok ? eidx[E_TOT + e] : 0;
    }

    const int r = tid >> 2, q = tid & 3;
    int eMine = e0 + r; if (eMine >= E_TOT) eMine = e0;
    const float* pE = edge_attr + (size_t)eMine * 128 + q * 16;        // + c*64
    const int nw = tid >> 1, hw = tid & 1;
    const __half* pW1e = g_W1eT + (size_t)nw * 128 + hw * 32;          // + c*64
    const __half* pW2  = g_W2T + (size_t)r * 256 + q * 16;             // + c*64

    const uint32_t sbX[2] = { smem_u32(smem + OF_X0), smem_u32(smem + OF_X1) };
    const uint32_t sbW[2] = { smem_u32(smem + OF_W0), smem_u32(smem + OF_W1B) };
    const uint32_t sbH    = smem_u32(smem + OF_H);
    const uint32_t dX  = (uint32_t)(r * XS + q * 16) * 2;
    const uint32_t dW1 = (uint32_t)(nw * WS + hw * 32) * 2;
    const uint32_t dW2 = (uint32_t)(r * WS + q * 16) * 2;

    const int aoff_row = lane & 15;
    const int aoff_k   = (lane >> 4) << 3;
    const int boff_n   = ((lane >> 4) << 3) + (lane & 7);
    const int boff_k   = ((lane >> 3) & 1) << 3;

    // prologue: stage chunk 0 (edge cols 0..63 + W1e panel 0)
    {
        #pragma unroll
        for (int s = 0; s < 4; s++) CP16(sbW[0] + dW1 + 16 * s, pW1e + 8 * s);
        CP_COMMIT();
        float4 fv[4];
        #pragma unroll
        for (int s = 0; s < 4; s++) fv[s] = *(const float4*)(pE + 4 * s);
        cvt_store32B(sbX[0] + dX, fv);
        CP_WAIT0();
    }
    __syncthreads();

    // ======== GEMM1e: accE[128x256] = E[128x128] @ W1e, 2 chunks of K=64 ========
    float acc[2][8][4];
    #pragma unroll
    for (int i = 0; i < 2; i++)
        #pragma unroll
        for (int j = 0; j < 8; j++)
            #pragma unroll
            for (int qq = 0; qq < 4; qq++) acc[i][j][qq] = 0.f;

    for (int c = 0; c < 2; c++) {
        const bool pre = (c == 0);
        float4 fv[4];
        if (pre) {
            #pragma unroll
            for (int s = 0; s < 4; s++) CP16(sbW[1] + dW1 + 16 * s, pW1e + 64 + 8 * s);
            CP_COMMIT();
            #pragma unroll
            for (int s = 0; s < 4; s++) fv[s] = *(const float4*)(pE + 64 + 4 * s);
        }
        const uint32_t xb = sbX[c], wb = sbW[c];
        #pragma unroll
        for (int ks = 0; ks < 4; ks++) {
            uint32_t A[2][4];
            #pragma unroll
            for (int i = 0; i < 2; i++)
                ldsm4(A[i], xb + (uint32_t)((wm * 32 + i * 16 + aoff_row) * XS + ks * 16 + aoff_k) * 2);
            #pragma unroll
            for (int jp = 0; jp < 4; jp++) {
                uint32_t B[4];
                ldsm4(B, wb + (uint32_t)((wn * 64 + jp * 16 + boff_n) * WS + ks * 16 + boff_k) * 2);
                mma16(acc[0][2 * jp],     A[0], B[0], B[1]);
                mma16(acc[1][2 * jp],     A[1], B[0], B[1]);
                mma16(acc[0][2 * jp + 1], A[0], B[2], B[3]);
                mma16(acc[1][2 * jp + 1], A[1], B[2], B[3]);
            }
        }
        if (pre) {
            cvt_store32B(sbX[1] + dX, fv);
            CP_WAIT0();
        }
        __syncthreads();
    }

    // ======== epilogue 1: H = fp16(relu(accE + Ps + Pr + b1)); stage W2 chunk 0 ========
    {
        __half* Hh = (__half*)(smem + OF_H);
        const int* sI = (const int*)(smem + OF_SI);
        const int* rI = (const int*)(smem + OF_RI);
        CP16(sbW[0] + dW2,      pW2);
        CP16(sbW[0] + dW2 + 16, pW2 + 8);
        CP_COMMIT();
        #pragma unroll
        for (int i = 0; i < 2; i++) {
            int r0 = wm * 32 + i * 16 + lr;
            const __half* P0s = g_P + (size_t)sI[r0] * 512;
            const __half* P0r = g_P + (size_t)rI[r0] * 512 + 256;
            const __half* P1s = g_P + (size_t)sI[r0 + 8] * 512;
            const __half* P1r = g_P + (size_t)rI[r0 + 8] * 512 + 256;
            #pragma unroll
            for (int j = 0; j < 8; j++) {
                int col = wn * 64 + j * 8 + 2 * lc;
                float2 ps0 = __half22float2(*(const __half2*)(P0s + col));
                float2 pr0 = __half22float2(*(const __half2*)(P0r + col));
                float2 ps1 = __half22float2(*(const __half2*)(P1s + col));
                float2 pr1 = __half22float2(*(const __half2*)(P1r + col));
                float g0 = smf[OF_B1 / 4 + col], g1 = smf[OF_B1 / 4 + col + 1];
                *(uint32_t*)(Hh + r0 * HS + col) =
                    pkh2(fmaxf(acc[i][j][0] + ps0.x + pr0.x + g0, 0.f),
                         fmaxf(acc[i][j][1] + ps0.y + pr0.y + g1, 0.f));
                *(uint32_t*)(Hh + (r0 + 8) * HS + col) =
                    pkh2(fmaxf(acc[i][j][2] + ps1.x + pr1.x + g0, 0.f),
                         fmaxf(acc[i][j][3] + ps1.y + pr1.y + g1, 0.f));
            }
        }
        CP_WAIT0();
    }
    __syncthreads();

    // ======== GEMM2: C2[128x128] = H[128x256] @ W2, 4 chunks of K=64 ========
    float acc2[2][4][4];
    #pragma unroll
    for (int i = 0; i < 2; i++)
        #pragma unroll
        for (int j = 0; j < 4; j++)
            #pragma unroll
            for (int qq = 0; qq < 4; qq++) acc2[i][j][qq] = 0.f;

    for (int c = 0; c < 4; c++) {
        if (c < 3) {
            CP16(sbW[(c + 1) & 1] + dW2,      pW2 + (c + 1) * 64);
            CP16(sbW[(c + 1) & 1] + dW2 + 16, pW2 + (c + 1) * 64 + 8);
            CP_COMMIT();
        }
        const uint32_t wb = sbW[c & 1];
        #pragma unroll
        for (int ks = 0; ks < 4; ks++) {
            uint32_t A[2][4];
            #pragma unroll
            for (int i = 0; i < 2; i++)
                ldsm4(A[i], sbH + (uint32_t)((wm * 32 + i * 16 + aoff_row) * HS + c * 64 + ks * 16 + aoff_k) * 2);
            #pragma unroll
            for (int jp = 0; jp < 2; jp++) {
                uint32_t B[4];
                ldsm4(B, wb + (uint32_t)((wn * 32 + jp * 16 + boff_n) * WS + ks * 16 + boff_k) * 2);
                mma16(acc2[0][2 * jp],     A[0], B[0], B[1]);
                mma16(acc2[1][2 * jp],     A[1], B[0], B[1]);
                mma16(acc2[0][2 * jp + 1], A[0], B[2], B[3]);
                mma16(acc2[1][2 * jp + 1], A[1], B[2], B[3]);
            }
        }
        if (c < 3) CP_WAIT0();
        __syncthreads();
    }

    // ======== epilogue 2: scratch = C2 + b2 ; LayerNorm -> out ========
    {
        float* Of = (float*)(smem + OF_H);
        #pragma unroll
        for (int i = 0; i < 2; i++) {
            int r0 = wm * 32 + i * 16 + lr;
            #pragma unroll
            for (int j = 0; j < 4; j++) {
                int col = wn * 32 + j * 8 + 2 * lc;
                float g0 = smf[OF_B2 / 4 + col], g1 = smf[OF_B2 / 4 + col + 1];
                Of[r0 * OS + col]           = acc2[i][j][0] + g0;
                Of[r0 * OS + col + 1]       = acc2[i][j][1] + g1;
                Of[(r0 + 8) * OS + col]     = acc2[i][j][2] + g0;
                Of[(r0 + 8) * OS + col + 1] = acc2[i][j][3] + g1;
            }
        }
    }
    __syncthreads();
    {
        const float* Of = (const float*)(smem + OF_H);
        float4 ga = *(const float4*)(smf + OF_G  / 4 + 4 * lane);
        float4 bt = *(const float4*)(smf + OF_BT / 4 + 4 * lane);
        #pragma unroll
        for (int rr = 0; rr < 8; rr++) {
            int row = wid * 8 + rr;
            int e = e0 + row;
            float4 v = *(const float4*)(Of + row * OS + 4 * lane);
            float s = v.x + v.y + v.z + v.w;
            float qs = v.x * v.x + v.y * v.y + v.z * v.z + v.w * v.w;
            #pragma unroll
            for (int o = 16; o > 0; o >>= 1) {
                s  += __shfl_xor_sync(0xffffffffu, s, o);
                qs += __shfl_xor_sync(0xffffffffu, qs, o);
            }
            float mean = s * (1.0f / 128.0f);
            float var  = qs * (1.0f / 128.0f) - mean * mean;
            float inv  = rsqrtf(var + 1e-5f);
            if (e < E_TOT) {
                float4 o4;
                o4.x = (v.x - mean) * inv * ga.x + bt.x;
                o4.y = (v.y - mean) * inv * ga.y + bt.y;
                o4.z = (v.z - mean) * inv * ga.z + bt.z;
                o4.w = (v.w - mean) * inv * ga.w + bt.w;
                *(float4*)(out + (size_t)e * 128 + 4 * lane) = o4;
            }
        }
    }
}

extern "C" void kernel_launch(void* const* d_in, const int* in_sizes, int n_in,
                              void* d_out, int out_size)
{
    (void)in_sizes; (void)n_in; (void)out_size;
    cvt_w_kernel<<<128, 256>>>((const float*)d_in[3], (const float*)d_in[5]);
    cudaFuncSetAttribute(precompute_kernel,
                         cudaFuncAttributeMaxDynamicSharedMemorySize, SMEM_PRE);
    precompute_kernel<<<dim3((N_NODES + 127) / 128, 2), 512, SMEM_PRE>>>(
        (const float*)d_in[0]);
    cudaFuncSetAttribute(edge_mlp_h,
                         cudaFuncAttributeMaxDynamicSharedMemorySize, SMEM_BYTES);
    dim3 grid((E_TOT + TILE_M - 1) / TILE_M);
    edge_mlp_h<<<grid, NTH, SMEM_BYTES>>>(
        (const float*)d_in[1],   // edge_contact_attr
        (const int*)  d_in[2],   // edge_contact_index
        (const float*)d_in[4],   // b1
        (const float*)d_in[6],   // b2
        (const float*)d_in[7],   // ln_gamma
        (const float*)d_in[8],   // ln_beta
        (float*)d_out);
}